// round 3
// baseline (speedup 1.0000x reference)
#include <cuda_runtime.h>

#define ALPHA 0.3f
#define EPSBN 1e-3f

#define B_ 512
#define NOISE_ 100
#define NC_ 10
#define EMB_ 50
#define DENSE_N 12544   /* 7*7*256 */
#define KIN 150
#define KIN_PAD 160

#define TM 64
#define TN 64
#define TK 16

// ---------------- scratch (device globals; BSS zero-init; padding never written) ----------
__device__ float g_xin[B_ * KIN_PAD];                 // dense input, zero-padded K
__device__ float g_scale1[DENSE_N];
__device__ float g_shift1[DENSE_N];
__device__ float g_sc1[NC_ * 256], g_sh1[NC_ * 256];
__device__ float g_sc2[NC_ * 128], g_sh2[NC_ * 128];
__device__ float g_x0[B_ * 11 * 11 * 306];            // [B,7,7,306] padded by 2 spatially
__device__ float g_h1[B_ * 9 * 9 * 256];              // [B,7,7,256] padded by 1
__device__ float g_h2[B_ * 16 * 16 * 128];            // [B,14,14,128] padded by 1
__device__ int   g_order[B_];
__device__ int   g_cstart[NC_ + 1];
__device__ int   g_aoff1[7650];
__device__ int   g_aoff2[4 * 2304];
__device__ int   g_wrow2[4 * 2304];

// ---------------- per-class bucketing (deterministic, stable) ----------------------------
__global__ void k_classify(const int* __restrict__ labels) {
    __shared__ int slab[B_];
    __shared__ int spre[NC_ + 1];
    int t = threadIdx.x;
    slab[t] = labels[t];
    __syncthreads();
    int c = slab[t];
    int rank = 0;
    for (int j = 0; j < t; j++) rank += (slab[j] == c) ? 1 : 0;
    if (t == 0) {
        int cnt[NC_];
        for (int i = 0; i < NC_; i++) cnt[i] = 0;
        for (int j = 0; j < B_; j++) cnt[slab[j]]++;
        int acc = 0;
        for (int i = 0; i < NC_; i++) { spre[i] = acc; g_cstart[i] = acc; acc += cnt[i]; }
        spre[NC_] = acc; g_cstart[NC_] = acc;
    }
    __syncthreads();
    g_order[spre[c] + rank] = t;
}

// ---------------- dense input concat [noise | emb[label]] --------------------------------
__global__ void k_xin(const float* __restrict__ noise, const float* __restrict__ emb,
                      const int* __restrict__ labels) {
    int idx = blockIdx.x * blockDim.x + threadIdx.x;
    if (idx >= B_ * KIN) return;
    int b = idx / KIN, k = idx - b * KIN;
    float v = (k < NOISE_) ? noise[b * NOISE_ + k]
                           : emb[labels[b] * EMB_ + (k - NOISE_)];
    g_xin[b * KIN_PAD + k] = v;
}

// ---------------- BN fold: scale = g*rsqrt(v+eps), shift = b - m*scale -------------------
__global__ void k_bnscale1(const float* __restrict__ g, const float* __restrict__ bb,
                           const float* __restrict__ m, const float* __restrict__ v) {
    int i = blockIdx.x * blockDim.x + threadIdx.x;
    if (i >= DENSE_N) return;
    float s = g[i] * rsqrtf(v[i] + EPSBN);
    g_scale1[i] = s;
    g_shift1[i] = bb[i] - m[i] * s;
}

__global__ void k_bnbranch(const float* __restrict__ G1, const float* __restrict__ Bb1,
                           const float* __restrict__ M1, const float* __restrict__ V1,
                           const float* __restrict__ G2, const float* __restrict__ Bb2,
                           const float* __restrict__ M2, const float* __restrict__ V2) {
    int i = blockIdx.x * blockDim.x + threadIdx.x;
    if (i < NC_ * 256) {
        float s = G1[i] * rsqrtf(V1[i] + EPSBN);
        g_sc1[i] = s; g_sh1[i] = Bb1[i] - M1[i] * s;
    } else if (i < NC_ * 256 + NC_ * 128) {
        int j = i - NC_ * 256;
        float s = G2[j] * rsqrtf(V2[j] + EPSBN);
        g_sc2[j] = s; g_sh2[j] = Bb2[j] - M2[j] * s;
    }
}

// ---------------- gather/weight-row offset tables ---------------------------------------
// ConvT1 (stride1, SAME, k=5, pad 2): out[h,w,co] = sum_{kh,kw,ci} x0p[h+kh, w+kw, ci]*K1[kh,kw,ci,co]
// ConvT2 parity decomposition (s=2, pad_a=3): out[2i+a] taps:
//   a==0: kh in {1,3},   dh = th-1 (th=0..1)
//   a==1: kh in {0,2,4}, dh = th-1 (th=0..2)
__global__ void k_tables() {
    int i = blockIdx.x * blockDim.x + threadIdx.x;
    if (i < 7650) {
        int kh = i / 1530, r = i - kh * 1530, kw = r / 306, ci = r - kw * 306;
        g_aoff1[i] = (kh * 11 + kw) * 306 + ci;
    } else if (i < 7650 + 4 * 2304) {
        int i2 = i - 7650;
        int par = i2 / 2304, q = i2 - par * 2304;
        int a = par >> 1, pb = par & 1;
        int nh = a ? 3 : 2, nw = pb ? 3 : 2;
        int Kp = nh * nw * 256;
        if (q < Kp) {
            int th = q / (nw * 256);
            int r = q - th * (nw * 256);
            int tw = r / 256, ci = r & 255;
            int kh = 2 * th + (a ? 0 : 1);
            int kw = 2 * tw + (pb ? 0 : 1);
            g_aoff2[par * 2304 + q] = (th * 9 + tw) * 256 + ci;   // (dh+1, dw+1) into padded h1
            g_wrow2[par * 2304 + q] = (kh * 5 + kw) * 256 + ci;   // row into K2[c] [25*256,128]
        }
    }
}

// ---------------- dense GEMM [512,150] x [150,12544] + bn + lrelu -> padded x0 -----------
__global__ __launch_bounds__(256) void k_dense(const float* __restrict__ Wd) {
    __shared__ float As[2][TK][TM + 4];
    __shared__ float Bs[2][TK][TN];
    int tid = threadIdx.x, tx = tid & 15, ty = tid >> 4;
    int row0 = blockIdx.y * TM;   // batch rows (512 = 8*64 exact)
    int col0 = blockIdx.x * TN;   // dense cols
    int ar = tid >> 2, ak = (tid & 3) * 4;
    int bkk = tid >> 4, bn = (tid & 15) * 4;
    const float* arow = g_xin + (size_t)(row0 + ar) * KIN_PAD;

    float acc[4][4];
#pragma unroll
    for (int i = 0; i < 4; i++)
#pragma unroll
        for (int j = 0; j < 4; j++) acc[i][j] = 0.f;

    const int nT = KIN_PAD / TK;   // 10
    float a_reg[4]; float4 b_reg;
    {
#pragma unroll
        for (int i = 0; i < 4; i++) a_reg[i] = arow[ak + i];
        int k = bkk;
        b_reg = (k < KIN) ? *(const float4*)(Wd + (size_t)k * DENSE_N + col0 + bn)
                          : make_float4(0.f, 0.f, 0.f, 0.f);
    }
    int buf = 0;
    for (int t = 0; t < nT; t++) {
#pragma unroll
        for (int i = 0; i < 4; i++) As[buf][ak + i][ar] = a_reg[i];
        *(float4*)&Bs[buf][bkk][bn] = b_reg;
        __syncthreads();
        if (t + 1 < nT) {
            int k0 = (t + 1) * TK;
#pragma unroll
            for (int i = 0; i < 4; i++) a_reg[i] = arow[k0 + ak + i];
            int k = k0 + bkk;
            b_reg = (k < KIN) ? *(const float4*)(Wd + (size_t)k * DENSE_N + col0 + bn)
                              : make_float4(0.f, 0.f, 0.f, 0.f);
        }
#pragma unroll
        for (int kk = 0; kk < TK; kk++) {
            float4 av = *(const float4*)&As[buf][kk][ty * 4];
            float4 bv = *(const float4*)&Bs[buf][kk][tx * 4];
            float aa[4] = {av.x, av.y, av.z, av.w};
            float bb2[4] = {bv.x, bv.y, bv.z, bv.w};
#pragma unroll
            for (int i = 0; i < 4; i++)
#pragma unroll
                for (int j = 0; j < 4; j++) acc[i][j] += aa[i] * bb2[j];
        }
        __syncthreads();
        buf ^= 1;
    }
    // epilogue: bn1 + lrelu, scatter into padded x0 (channels 0..255)
#pragma unroll
    for (int i = 0; i < 4; i++) {
        int b = row0 + ty * 4 + i;
#pragma unroll
        for (int j = 0; j < 4; j++) {
            int jc = col0 + tx * 4 + j;
            float y = acc[i][j] * g_scale1[jc] + g_shift1[jc];
            y = (y >= 0.f) ? y : ALPHA * y;
            int h = jc / 1792;
            int w = (jc >> 8) % 7;
            int ch = jc & 255;
            g_x0[((size_t)(b * 11 + h + 2) * 11 + (w + 2)) * 306 + ch] = y;
        }
    }
}

// ---------------- append embedding channels 256..305 to x0 -------------------------------
__global__ void k_embx0(const float* __restrict__ emb, const int* __restrict__ labels) {
    int idx = blockIdx.x * blockDim.x + threadIdx.x;
    if (idx >= B_ * 49 * EMB_) return;
    int e = idx % EMB_;
    int rest = idx / EMB_;
    int pos = rest % 49, b = rest / 49;
    int h = pos / 7, w = pos - h * 7;
    g_x0[((size_t)(b * 11 + h + 2) * 11 + (w + 2)) * 306 + 256 + e] = emb[labels[b] * EMB_ + e];
}

// ---------------- generic class-routed gather-GEMM (ConvT1, ConvT2 parities) -------------
// mode 0: ConvT1;  mode 1..4: ConvT2 parity (a= (mode-1)>>1, pb = (mode-1)&1)
__global__ __launch_bounds__(256) void k_convgemm(int mode, const float* __restrict__ Wfull) {
    const float* A; int a_bs, a_pw, a_pc; const int* aoff; int w_cs; const int* wrow;
    int K, N; const float* sc; const float* sh; float* O;
    int o_bs, o_rs, o_h0, o_hs, o_w0, o_ws, o_cs;
    if (mode == 0) {
        A = g_x0; a_bs = 11 * 11 * 306; a_pw = 11; a_pc = 306;
        aoff = g_aoff1; w_cs = 5 * 5 * 306 * 256; wrow = 0;
        K = 7650; N = 256; sc = g_sc1; sh = g_sh1; O = g_h1;
        o_bs = 9 * 9 * 256; o_rs = 9 * 256; o_h0 = 1; o_hs = 1; o_w0 = 1; o_ws = 1; o_cs = 256;
    } else {
        int par = mode - 1, a = par >> 1, pb = par & 1;
        A = g_h1; a_bs = 9 * 9 * 256; a_pw = 9; a_pc = 256;
        aoff = g_aoff2 + par * 2304; w_cs = 5 * 5 * 256 * 128; wrow = g_wrow2 + par * 2304;
        K = (a ? 3 : 2) * (pb ? 3 : 2) * 256; N = 128; sc = g_sc2; sh = g_sh2; O = g_h2;
        o_bs = 16 * 16 * 128; o_rs = 16 * 128; o_h0 = a + 1; o_hs = 2; o_w0 = pb + 1; o_ws = 2; o_cs = 128;
    }
    int c = blockIdx.z;
    int s0 = g_cstart[c];
    int rows = (g_cstart[c + 1] - s0) * 49;
    int row0 = blockIdx.y * TM;
    if (row0 >= rows) return;
    int col0 = blockIdx.x * TN;

    __shared__ float As[2][TK][TM + 4];
    __shared__ float Bs[2][TK][TN];
    int tid = threadIdx.x, tx = tid & 15, ty = tid >> 4;
    int ar = tid >> 2, ak = (tid & 3) * 4;
    int bkk = tid >> 4, bn = (tid & 15) * 4;

    const float* abase = 0;
    {
        int r = row0 + ar;
        if (r < rows) {
            int sl = r / 49, pos = r - sl * 49;
            int b = g_order[s0 + sl];
            int h = pos / 7, w = pos - h * 7;
            abase = A + (size_t)b * a_bs + (h * a_pw + w) * a_pc;
        }
    }
    const float* wc = Wfull + (size_t)c * w_cs;

    float acc[4][4];
#pragma unroll
    for (int i = 0; i < 4; i++)
#pragma unroll
        for (int j = 0; j < 4; j++) acc[i][j] = 0.f;

    int nT = (K + TK - 1) / TK;
    float a_reg[4]; float4 b_reg;
    {
#pragma unroll
        for (int i = 0; i < 4; i++) {
            int k = ak + i;
            a_reg[i] = (abase && k < K) ? __ldg(abase + aoff[k]) : 0.f;
        }
        int k = bkk;
        if (k < K) {
            int wr = wrow ? wrow[k] : k;
            b_reg = *(const float4*)(wc + (size_t)wr * N + col0 + bn);
        } else b_reg = make_float4(0.f, 0.f, 0.f, 0.f);
    }
    int buf = 0;
    for (int t = 0; t < nT; t++) {
#pragma unroll
        for (int i = 0; i < 4; i++) As[buf][ak + i][ar] = a_reg[i];
        *(float4*)&Bs[buf][bkk][bn] = b_reg;
        __syncthreads();
        if (t + 1 < nT) {
            int k0 = (t + 1) * TK;
#pragma unroll
            for (int i = 0; i < 4; i++) {
                int k = k0 + ak + i;
                a_reg[i] = (abase && k < K) ? __ldg(abase + aoff[k]) : 0.f;
            }
            int k = k0 + bkk;
            if (k < K) {
                int wr = wrow ? wrow[k] : k;
                b_reg = *(const float4*)(wc + (size_t)wr * N + col0 + bn);
            } else b_reg = make_float4(0.f, 0.f, 0.f, 0.f);
        }
#pragma unroll
        for (int kk = 0; kk < TK; kk++) {
            float4 av = *(const float4*)&As[buf][kk][ty * 4];
            float4 bv = *(const float4*)&Bs[buf][kk][tx * 4];
            float aa[4] = {av.x, av.y, av.z, av.w};
            float bb2[4] = {bv.x, bv.y, bv.z, bv.w};
#pragma unroll
            for (int i = 0; i < 4; i++)
#pragma unroll
                for (int j = 0; j < 4; j++) acc[i][j] += aa[i] * bb2[j];
        }
        __syncthreads();
        buf ^= 1;
    }
    // epilogue: bn + lrelu, scatter to padded output
#pragma unroll
    for (int i = 0; i < 4; i++) {
        int r = row0 + ty * 4 + i;
        if (r >= rows) continue;
        int sl = r / 49, pos = r - sl * 49;
        int b = g_order[s0 + sl];
        int h = pos / 7, w = pos - h * 7;
        size_t ob = (size_t)b * o_bs + (size_t)(o_h0 + h * o_hs) * o_rs
                  + (size_t)(o_w0 + w * o_ws) * o_cs;
#pragma unroll
        for (int j = 0; j < 4; j++) {
            int co = col0 + tx * 4 + j;
            float y = acc[i][j] * sc[c * N + co] + sh[c * N + co];
            O[ob + co] = (y >= 0.f) ? y : ALPHA * y;
        }
    }
}

// ---------------- ConvT3 (N=1) + tanh ----------------------------------------------------
__global__ __launch_bounds__(256) void k_convt3(const float* __restrict__ K3,
                                                const int* __restrict__ labels,
                                                float* __restrict__ out) {
    int b = blockIdx.x;
    int c = labels[b];
    __shared__ float Ks[5 * 5 * 128];
    for (int i = threadIdx.x; i < 5 * 5 * 128; i += blockDim.x)
        Ks[i] = K3[c * (5 * 5 * 128) + i];
    __syncthreads();
    const float* hb = g_h2 + (size_t)b * 16 * 16 * 128;
    for (int p = threadIdx.x; p < 784; p += blockDim.x) {
        int oh = p / 28, ow = p - oh * 28;
        int i = oh >> 1, a = oh & 1, j = ow >> 1, pb = ow & 1;
        int nh = a ? 3 : 2, nw = pb ? 3 : 2;
        float acc = 0.f;
        for (int th = 0; th < nh; th++) {
            int kh = 2 * th + (a ? 0 : 1);
            int ph = i + th;                    // padded row = i + dh + 1
            for (int tw = 0; tw < nw; tw++) {
                int kw = 2 * tw + (pb ? 0 : 1);
                int pw = j + tw;
                const float* xp = hb + (size_t)(ph * 16 + pw) * 128;
                const float* wp = Ks + (kh * 5 + kw) * 128;
#pragma unroll
                for (int ci = 0; ci < 128; ci += 4) {
                    float4 xv = *(const float4*)(xp + ci);
                    float4 wv = *(const float4*)(wp + ci);
                    acc += xv.x * wv.x + xv.y * wv.y + xv.z * wv.z + xv.w * wv.w;
                }
            }
        }
        out[(size_t)b * 784 + p] = tanhf(acc);
    }
}

// ---------------- launch ----------------------------------------------------------------
extern "C" void kernel_launch(void* const* d_in, const int* in_sizes, int n_in,
                              void* d_out, int out_size) {
    const float* noise = (const float*)d_in[0];
    const int*   labels = (const int*)d_in[1];
    const float* emb  = (const float*)d_in[2];
    const float* Wd   = (const float*)d_in[3];
    const float* bn1_g = (const float*)d_in[4];
    const float* bn1_b = (const float*)d_in[5];
    const float* bn1_m = (const float*)d_in[6];
    const float* bn1_v = (const float*)d_in[7];
    const float* K1 = (const float*)d_in[8];
    const float* G1 = (const float*)d_in[9];
    const float* B1 = (const float*)d_in[10];
    const float* M1 = (const float*)d_in[11];
    const float* V1 = (const float*)d_in[12];
    const float* K2 = (const float*)d_in[13];
    const float* G2 = (const float*)d_in[14];
    const float* B2 = (const float*)d_in[15];
    const float* M2 = (const float*)d_in[16];
    const float* V2 = (const float*)d_in[17];
    const float* K3 = (const float*)d_in[18];
    float* out = (float*)d_out;

    k_classify<<<1, B_>>>(labels);
    k_xin<<<(B_ * KIN + 255) / 256, 256>>>(noise, emb, labels);
    k_bnscale1<<<(DENSE_N + 255) / 256, 256>>>(bn1_g, bn1_b, bn1_m, bn1_v);
    k_bnbranch<<<(NC_ * 256 + NC_ * 128 + 255) / 256, 256>>>(G1, B1, M1, V1, G2, B2, M2, V2);
    k_tables<<<(7650 + 4 * 2304 + 255) / 256, 256>>>();

    k_dense<<<dim3(DENSE_N / TN, B_ / TM), 256>>>(Wd);
    k_embx0<<<(B_ * 49 * EMB_ + 255) / 256, 256>>>(emb, labels);

    // ConvT1: worst-case rows per class = 512*49 -> 392 row tiles; inactive blocks early-exit
    k_convgemm<<<dim3(256 / TN, (B_ * 49 + TM - 1) / TM, NC_), 256>>>(0, K1);

    // ConvT2: 4 parity GEMMs
    for (int par = 0; par < 4; par++)
        k_convgemm<<<dim3(128 / TN, (B_ * 49 + TM - 1) / TM, NC_), 256>>>(1 + par, K2);

    k_convt3<<<B_, 256>>>(K3, labels, out);
    (void)in_sizes; (void)n_in; (void)out_size;
}

// round 6
// speedup vs baseline: 1.0807x; 1.0807x over previous
#include <cuda_runtime.h>

#define ALPHA 0.3f
#define EPSBN 1e-3f

#define B_ 512
#define NOISE_ 100
#define NC_ 10
#define EMB_ 50
#define DENSE_N 12544   /* 7*7*256 */
#define KIN 150
#define KIN_PAD 160

/* dense GEMM tile */
#define TM 64
#define TN 64
#define TK 16

/* conv GEMM tile (packed-FMA path) */
#define GTM 128
#define GTN 128
#define GTK 16

typedef unsigned long long u64;

__device__ __forceinline__ u64 pk2(float lo, float hi) {
    u64 r;
    asm("mov.b64 %0, {%1, %2};" : "=l"(r) : "f"(lo), "f"(hi));
    return r;
}
__device__ __forceinline__ u64 ffma2(u64 a, u64 b, u64 c) {
    u64 d;
    asm("fma.rn.f32x2 %0, %1, %2, %3;" : "=l"(d) : "l"(a), "l"(b), "l"(c));
    return d;
}
__device__ __forceinline__ void upk2(u64 v, float& lo, float& hi) {
    asm("mov.b64 {%0, %1}, %2;" : "=f"(lo), "=f"(hi) : "l"(v));
}

// ---------------- scratch (device globals; BSS zero-init; padding never written) ----------
__device__ float g_xin[B_ * KIN_PAD];                 // dense input, zero-padded K
__device__ float g_scale1[DENSE_N];
__device__ float g_shift1[DENSE_N];
__device__ float g_sc1[NC_ * 256], g_sh1[NC_ * 256];
__device__ float g_sc2[NC_ * 128], g_sh2[NC_ * 128];
__device__ float g_x0[B_ * 11 * 11 * 306];            // [B,7,7,306] padded by 2 spatially
__device__ float g_h1[B_ * 9 * 9 * 256];              // [B,7,7,256] padded by 1
__device__ float g_h2[B_ * 16 * 16 * 128];            // [B,14,14,128] padded by 1
__device__ int   g_order[B_];
__device__ int   g_cstart[NC_ + 1];
__device__ int   g_aoff1[7650];
__device__ int   g_aoff2[4 * 2304];
__device__ int   g_wrow2[4 * 2304];

// ---------------- per-class bucketing (deterministic, stable) ----------------------------
__global__ void k_classify(const int* __restrict__ labels) {
    __shared__ int slab[B_];
    __shared__ int spre[NC_ + 1];
    int t = threadIdx.x;
    slab[t] = labels[t];
    __syncthreads();
    int c = slab[t];
    int rank = 0;
    for (int j = 0; j < t; j++) rank += (slab[j] == c) ? 1 : 0;
    if (t == 0) {
        int cnt[NC_];
        for (int i = 0; i < NC_; i++) cnt[i] = 0;
        for (int j = 0; j < B_; j++) cnt[slab[j]]++;
        int acc = 0;
        for (int i = 0; i < NC_; i++) { spre[i] = acc; g_cstart[i] = acc; acc += cnt[i]; }
        spre[NC_] = acc; g_cstart[NC_] = acc;
    }
    __syncthreads();
    g_order[spre[c] + rank] = t;
}

// ---------------- dense input concat [noise | emb[label]] --------------------------------
__global__ void k_xin(const float* __restrict__ noise, const float* __restrict__ emb,
                      const int* __restrict__ labels) {
    int idx = blockIdx.x * blockDim.x + threadIdx.x;
    if (idx >= B_ * KIN) return;
    int b = idx / KIN, k = idx - b * KIN;
    float v = (k < NOISE_) ? noise[b * NOISE_ + k]
                           : emb[labels[b] * EMB_ + (k - NOISE_)];
    g_xin[b * KIN_PAD + k] = v;
}

// ---------------- BN fold: scale = g*rsqrt(v+eps), shift = b - m*scale -------------------
__global__ void k_bnscale1(const float* __restrict__ g, const float* __restrict__ bb,
                           const float* __restrict__ m, const float* __restrict__ v) {
    int i = blockIdx.x * blockDim.x + threadIdx.x;
    if (i >= DENSE_N) return;
    float s = g[i] * rsqrtf(v[i] + EPSBN);
    g_scale1[i] = s;
    g_shift1[i] = bb[i] - m[i] * s;
}

__global__ void k_bnbranch(const float* __restrict__ G1, const float* __restrict__ Bb1,
                           const float* __restrict__ M1, const float* __restrict__ V1,
                           const float* __restrict__ G2, const float* __restrict__ Bb2,
                           const float* __restrict__ M2, const float* __restrict__ V2) {
    int i = blockIdx.x * blockDim.x + threadIdx.x;
    if (i < NC_ * 256) {
        float s = G1[i] * rsqrtf(V1[i] + EPSBN);
        g_sc1[i] = s; g_sh1[i] = Bb1[i] - M1[i] * s;
    } else if (i < NC_ * 256 + NC_ * 128) {
        int j = i - NC_ * 256;
        float s = G2[j] * rsqrtf(V2[j] + EPSBN);
        g_sc2[j] = s; g_sh2[j] = Bb2[j] - M2[j] * s;
    }
}

// ---------------- gather/weight-row offset tables ---------------------------------------
__global__ void k_tables() {
    int i = blockIdx.x * blockDim.x + threadIdx.x;
    if (i < 7650) {
        int kh = i / 1530, r = i - kh * 1530, kw = r / 306, ci = r - kw * 306;
        g_aoff1[i] = (kh * 11 + kw) * 306 + ci;
    } else if (i < 7650 + 4 * 2304) {
        int i2 = i - 7650;
        int par = i2 / 2304, q = i2 - par * 2304;
        int a = par >> 1, pb = par & 1;
        int nh = a ? 3 : 2, nw = pb ? 3 : 2;
        int Kp = nh * nw * 256;
        if (q < Kp) {
            int th = q / (nw * 256);
            int r = q - th * (nw * 256);
            int tw = r / 256, ci = r & 255;
            int kh = 2 * th + (a ? 0 : 1);
            int kw = 2 * tw + (pb ? 0 : 1);
            g_aoff2[par * 2304 + q] = (th * 9 + tw) * 256 + ci;   // (dh+1, dw+1) into padded h1
            g_wrow2[par * 2304 + q] = (kh * 5 + kw) * 256 + ci;   // row into K2[c] [25*256,128]
        }
    }
}

// ---------------- dense GEMM [512,150] x [150,12544] + bn + lrelu -> padded x0 -----------
__global__ __launch_bounds__(256) void k_dense(const float* __restrict__ Wd) {
    __shared__ float As[2][TK][TM + 4];
    __shared__ float Bs[2][TK][TN];
    int tid = threadIdx.x, tx = tid & 15, ty = tid >> 4;
    int row0 = blockIdx.y * TM;   // batch rows (512 = 8*64 exact)
    int col0 = blockIdx.x * TN;   // dense cols
    int ar = tid >> 2, ak = (tid & 3) * 4;
    int bkk = tid >> 4, bn = (tid & 15) * 4;
    const float* arow = g_xin + (size_t)(row0 + ar) * KIN_PAD;

    u64 acc[4][2];
#pragma unroll
    for (int i = 0; i < 4; i++) { acc[i][0] = 0ull; acc[i][1] = 0ull; }

    const int nT = KIN_PAD / TK;   // 10
    float a_reg[4]; float4 b_reg;
    {
#pragma unroll
        for (int i = 0; i < 4; i++) a_reg[i] = arow[ak + i];
        int k = bkk;
        b_reg = (k < KIN) ? *(const float4*)(Wd + (size_t)k * DENSE_N + col0 + bn)
                          : make_float4(0.f, 0.f, 0.f, 0.f);
    }
    int buf = 0;
    for (int t = 0; t < nT; t++) {
#pragma unroll
        for (int i = 0; i < 4; i++) As[buf][ak + i][ar] = a_reg[i];
        *(float4*)&Bs[buf][bkk][bn] = b_reg;
        __syncthreads();
        if (t + 1 < nT) {
            int k0 = (t + 1) * TK;
#pragma unroll
            for (int i = 0; i < 4; i++) a_reg[i] = arow[k0 + ak + i];
            int k = k0 + bkk;
            b_reg = (k < KIN) ? *(const float4*)(Wd + (size_t)k * DENSE_N + col0 + bn)
                              : make_float4(0.f, 0.f, 0.f, 0.f);
        }
#pragma unroll
        for (int kk = 0; kk < TK; kk++) {
            float4 av = *(const float4*)&As[buf][kk][ty * 4];
            u64 b0 = *(const u64*)&Bs[buf][kk][tx * 4];
            u64 b1 = *(const u64*)&Bs[buf][kk][tx * 4 + 2];
            float aa[4] = {av.x, av.y, av.z, av.w};
#pragma unroll
            for (int i = 0; i < 4; i++) {
                u64 ad = pk2(aa[i], aa[i]);
                acc[i][0] = ffma2(ad, b0, acc[i][0]);
                acc[i][1] = ffma2(ad, b1, acc[i][1]);
            }
        }
        __syncthreads();
        buf ^= 1;
    }
    // epilogue: bn1 + lrelu, scatter into padded x0 (channels 0..255)
#pragma unroll
    for (int i = 0; i < 4; i++) {
        int b = row0 + ty * 4 + i;
        float y4[4];
        upk2(acc[i][0], y4[0], y4[1]);
        upk2(acc[i][1], y4[2], y4[3]);
#pragma unroll
        for (int j = 0; j < 4; j++) {
            int jc = col0 + tx * 4 + j;
            float y = y4[j] * g_scale1[jc] + g_shift1[jc];
            y = (y >= 0.f) ? y : ALPHA * y;
            int h = jc / 1792;
            int w = (jc >> 8) % 7;
            int ch = jc & 255;
            g_x0[((size_t)(b * 11 + h + 2) * 11 + (w + 2)) * 306 + ch] = y;
        }
    }
}

// ---------------- append embedding channels 256..305 to x0 -------------------------------
__global__ void k_embx0(const float* __restrict__ emb, const int* __restrict__ labels) {
    int idx = blockIdx.x * blockDim.x + threadIdx.x;
    if (idx >= B_ * 49 * EMB_) return;
    int e = idx % EMB_;
    int rest = idx / EMB_;
    int pos = rest % 49, b = rest / 49;
    int h = pos / 7, w = pos - h * 7;
    g_x0[((size_t)(b * 11 + h + 2) * 11 + (w + 2)) * 306 + 256 + e] = emb[labels[b] * EMB_ + e];
}

// ---------------- class-routed gather-GEMM, 128x128 tile, packed f32x2 FMA ---------------
// mode 0: ConvT1 (col tile = blockIdx.x); mode 1: ConvT2, parity = blockIdx.x
__global__ __launch_bounds__(256, 2) void k_convgemm(int mode, const float* __restrict__ Wfull) {
    const float* A; int a_bs, a_pw, a_pc; const int* aoff; int w_cs; const int* wrow;
    int K, N; const float* sc; const float* sh; float* O;
    int o_bs, o_rs, o_h0, o_hs, o_w0, o_ws, o_cs, col0;
    if (mode == 0) {
        A = g_x0; a_bs = 11 * 11 * 306; a_pw = 11; a_pc = 306;
        aoff = g_aoff1; w_cs = 5 * 5 * 306 * 256; wrow = 0;
        K = 7650; N = 256; sc = g_sc1; sh = g_sh1; O = g_h1;
        o_bs = 9 * 9 * 256; o_rs = 9 * 256; o_h0 = 1; o_hs = 1; o_w0 = 1; o_ws = 1; o_cs = 256;
        col0 = blockIdx.x * GTN;
    } else {
        int par = blockIdx.x, a = par >> 1, pb = par & 1;
        A = g_h1; a_bs = 9 * 9 * 256; a_pw = 9; a_pc = 256;
        aoff = g_aoff2 + par * 2304; w_cs = 5 * 5 * 256 * 128; wrow = g_wrow2 + par * 2304;
        K = (a ? 3 : 2) * (pb ? 3 : 2) * 256; N = 128; sc = g_sc2; sh = g_sh2; O = g_h2;
        o_bs = 16 * 16 * 128; o_rs = 16 * 128; o_h0 = a + 1; o_hs = 2; o_w0 = pb + 1; o_ws = 2; o_cs = 128;
        col0 = 0;
    }
    int c = blockIdx.z;
    int s0 = g_cstart[c];
    int rows = (g_cstart[c + 1] - s0) * 49;
    int row0 = blockIdx.y * GTM;
    if (row0 >= rows) return;

    __shared__ float As[2][GTK][GTM + 4];
    __shared__ float Bs[2][GTK][GTN];
    int tid = threadIdx.x;
    int tx = tid & 15, ty = tid >> 4;
    int ar = tid & 127, ak0 = (tid >> 7) * 8;   // A fill: row ar, k-range [ak0, ak0+8)
    int bk = tid >> 4, bn = (tid & 15) * 8;     // B fill: k row bk, 8 cols at bn

    const float* abase = 0;
    {
        int r = row0 + ar;
        if (r < rows) {
            int sl = r / 49, pos = r - sl * 49;
            int b = g_order[s0 + sl];
            int h = pos / 7, w = pos - h * 7;
            abase = A + (size_t)b * a_bs + (h * a_pw + w) * a_pc;
        }
    }
    const float* wc = Wfull + (size_t)c * w_cs;

    u64 acc[8][4];
#pragma unroll
    for (int i = 0; i < 8; i++)
#pragma unroll
        for (int j = 0; j < 4; j++) acc[i][j] = 0ull;

    int nT = (K + GTK - 1) / GTK;
    float a_reg[8]; float4 b0r, b1r;
    {
#pragma unroll
        for (int i = 0; i < 8; i++) {
            int k = ak0 + i;
            a_reg[i] = (abase && k < K) ? __ldg(abase + aoff[k]) : 0.f;
        }
        int k = bk;
        if (k < K) {
            int wr = wrow ? wrow[k] : k;
            const float* p = wc + (size_t)wr * N + col0 + bn;
            b0r = *(const float4*)p; b1r = *(const float4*)(p + 4);
        } else { b0r = make_float4(0.f,0.f,0.f,0.f); b1r = b0r; }
    }
    int buf = 0;
    for (int t = 0; t < nT; t++) {
#pragma unroll
        for (int i = 0; i < 8; i++) As[buf][ak0 + i][ar] = a_reg[i];
        *(float4*)&Bs[buf][bk][bn] = b0r;
        *(float4*)&Bs[buf][bk][bn + 4] = b1r;
        __syncthreads();
        if (t + 1 < nT) {
            int k0 = (t + 1) * GTK;
#pragma unroll
            for (int i = 0; i < 8; i++) {
                int k = k0 + ak0 + i;
                a_reg[i] = (abase && k < K) ? __ldg(abase + aoff[k]) : 0.f;
            }
            int k = k0 + bk;
            if (k < K) {
                int wr = wrow ? wrow[k] : k;
                const float* p = wc + (size_t)wr * N + col0 + bn;
                b0r = *(const float4*)p; b1r = *(const float4*)(p + 4);
            } else { b0r = make_float4(0.f,0.f,0.f,0.f); b1r = b0r; }
        }
#pragma unroll
        for (int kk = 0; kk < GTK; kk++) {
            float4 a0 = *(const float4*)&As[buf][kk][ty * 8];
            float4 a1 = *(const float4*)&As[buf][kk][ty * 8 + 4];
            u64 bq0 = *(const u64*)&Bs[buf][kk][tx * 8];
            u64 bq1 = *(const u64*)&Bs[buf][kk][tx * 8 + 2];
            u64 bq2 = *(const u64*)&Bs[buf][kk][tx * 8 + 4];
            u64 bq3 = *(const u64*)&Bs[buf][kk][tx * 8 + 6];
            float av[8] = {a0.x, a0.y, a0.z, a0.w, a1.x, a1.y, a1.z, a1.w};
#pragma unroll
            for (int i = 0; i < 8; i++) {
                u64 ad = pk2(av[i], av[i]);
                acc[i][0] = ffma2(ad, bq0, acc[i][0]);
                acc[i][1] = ffma2(ad, bq1, acc[i][1]);
                acc[i][2] = ffma2(ad, bq2, acc[i][2]);
                acc[i][3] = ffma2(ad, bq3, acc[i][3]);
            }
        }
        __syncthreads();
        buf ^= 1;
    }
    // epilogue: bn + lrelu, scatter to padded output (8 cols contiguous -> 2x float4)
    int co0 = col0 + tx * 8;
    float sc8[8], sh8[8];
#pragma unroll
    for (int j = 0; j < 8; j++) { sc8[j] = sc[c * N + co0 + j]; sh8[j] = sh[c * N + co0 + j]; }
#pragma unroll
    for (int i = 0; i < 8; i++) {
        int r = row0 + ty * 8 + i;
        if (r >= rows) continue;
        int sl = r / 49, pos = r - sl * 49;
        int b = g_order[s0 + sl];
        int h = pos / 7, w = pos - h * 7;
        size_t ob = (size_t)b * o_bs + (size_t)(o_h0 + h * o_hs) * o_rs
                  + (size_t)(o_w0 + w * o_ws) * o_cs;
        float y[8];
#pragma unroll
        for (int j = 0; j < 4; j++) upk2(acc[i][j], y[2 * j], y[2 * j + 1]);
#pragma unroll
        for (int j = 0; j < 8; j++) {
            float v = y[j] * sc8[j] + sh8[j];
            y[j] = (v >= 0.f) ? v : ALPHA * v;
        }
        *(float4*)&O[ob + co0]     = make_float4(y[0], y[1], y[2], y[3]);
        *(float4*)&O[ob + co0 + 4] = make_float4(y[4], y[5], y[6], y[7]);
    }
}

// ---------------- ConvT3 (N=1) + tanh ----------------------------------------------------
__global__ __launch_bounds__(256) void k_convt3(const float* __restrict__ K3,
                                                const int* __restrict__ labels,
                                                float* __restrict__ out) {
    int b = blockIdx.x;
    int c = labels[b];
    __shared__ float Ks[5 * 5 * 128];
    for (int i = threadIdx.x; i < 5 * 5 * 128; i += blockDim.x)
        Ks[i] = K3[c * (5 * 5 * 128) + i];
    __syncthreads();
    const float* hb = g_h2 + (size_t)b * 16 * 16 * 128;
    for (int p = threadIdx.x; p < 784; p += blockDim.x) {
        int oh = p / 28, ow = p - oh * 28;
        int i = oh >> 1, a = oh & 1, j = ow >> 1, pb = ow & 1;
        int nh = a ? 3 : 2, nw = pb ? 3 : 2;
        float acc = 0.f;
        for (int th = 0; th < nh; th++) {
            int kh = 2 * th + (a ? 0 : 1);
            int ph = i + th;
            for (int tw = 0; tw < nw; tw++) {
                int kw = 2 * tw + (pb ? 0 : 1);
                int pw = j + tw;
                const float* xp = hb + (size_t)(ph * 16 + pw) * 128;
                const float* wp = Ks + (kh * 5 + kw) * 128;
#pragma unroll
                for (int ci = 0; ci < 128; ci += 4) {
                    float4 xv = *(const float4*)(xp + ci);
                    float4 wv = *(const float4*)(wp + ci);
                    acc += xv.x * wv.x + xv.y * wv.y + xv.z * wv.z + xv.w * wv.w;
                }
            }
        }
        out[(size_t)b * 784 + p] = tanhf(acc);
    }
}

// ---------------- launch ----------------------------------------------------------------
extern "C" void kernel_launch(void* const* d_in, const int* in_sizes, int n_in,
                              void* d_out, int out_size) {
    const float* noise = (const float*)d_in[0];
    const int*   labels = (const int*)d_in[1];
    const float* emb  = (const float*)d_in[2];
    const float* Wd   = (const float*)d_in[3];
    const float* bn1_g = (const float*)d_in[4];
    const float* bn1_b = (const float*)d_in[5];
    const float* bn1_m = (const float*)d_in[6];
    const float* bn1_v = (const float*)d_in[7];
    const float* K1 = (const float*)d_in[8];
    const float* G1 = (const float*)d_in[9];
    const float* B1 = (const float*)d_in[10];
    const float* M1 = (const float*)d_in[11];
    const float* V1 = (const float*)d_in[12];
    const float* K2 = (const float*)d_in[13];
    const float* G2 = (const float*)d_in[14];
    const float* B2 = (const float*)d_in[15];
    const float* M2 = (const float*)d_in[16];
    const float* V2 = (const float*)d_in[17];
    const float* K3 = (const float*)d_in[18];
    float* out = (float*)d_out;

    k_classify<<<1, B_>>>(labels);
    k_xin<<<(B_ * KIN + 255) / 256, 256>>>(noise, emb, labels);
    k_bnscale1<<<(DENSE_N + 255) / 256, 256>>>(bn1_g, bn1_b, bn1_m, bn1_v);
    k_bnbranch<<<(NC_ * 256 + NC_ * 128 + 255) / 256, 256>>>(G1, B1, M1, V1, G2, B2, M2, V2);
    k_tables<<<(7650 + 4 * 2304 + 255) / 256, 256>>>();

    k_dense<<<dim3(DENSE_N / TN, B_ / TM), 256>>>(Wd);
    k_embx0<<<(B_ * 49 * EMB_ + 255) / 256, 256>>>(emb, labels);

    // ConvT1: 2 col tiles x 196 worst-case row tiles x 10 classes; empty tiles early-exit
    k_convgemm<<<dim3(256 / GTN, (B_ * 49 + GTM - 1) / GTM, NC_), 256>>>(0, K1);

    // ConvT2: all 4 parities in ONE launch (blockIdx.x = parity)
    k_convgemm<<<dim3(4, (B_ * 49 + GTM - 1) / GTM, NC_), 256>>>(1, K2);

    k_convt3<<<B_, 256>>>(K3, labels, out);
    (void)in_sizes; (void)n_in; (void)out_size;
}

// round 7
// speedup vs baseline: 1.2023x; 1.1126x over previous
#include <cuda_runtime.h>
#include <cuda_bf16.h>

#define ALPHA 0.3f
#define EPSBN 1e-3f

#define B_ 512
#define NOISE_ 100
#define NC_ 10
#define EMB_ 50
#define DENSE_N 12544   /* 7*7*256 */
#define KIN 150
#define KIN_PAD 160

/* dense GEMM tile */
#define TM 64
#define TN 64
#define TK 16

/* mma smem pitch (bf16 elems per row) */
#define PIT 40

typedef unsigned int u32;
typedef unsigned long long u64;

__device__ __forceinline__ u64 pk2(float lo, float hi) {
    u64 r; asm("mov.b64 %0, {%1, %2};" : "=l"(r) : "f"(lo), "f"(hi)); return r;
}
__device__ __forceinline__ u64 ffma2(u64 a, u64 b, u64 c) {
    u64 d; asm("fma.rn.f32x2 %0, %1, %2, %3;" : "=l"(d) : "l"(a), "l"(b), "l"(c)); return d;
}
__device__ __forceinline__ void upk2(u64 v, float& lo, float& hi) {
    asm("mov.b64 {%0, %1}, %2;" : "=f"(lo), "=f"(hi) : "l"(v));
}
__device__ __forceinline__ void mma16816(float* c, u32 a0, u32 a1, u32 a2, u32 a3,
                                         u32 b0, u32 b1) {
    asm volatile("mma.sync.aligned.m16n8k16.row.col.f32.bf16.bf16.f32 "
                 "{%0,%1,%2,%3}, {%4,%5,%6,%7}, {%8,%9}, {%0,%1,%2,%3};"
                 : "+f"(c[0]), "+f"(c[1]), "+f"(c[2]), "+f"(c[3])
                 : "r"(a0), "r"(a1), "r"(a2), "r"(a3), "r"(b0), "r"(b1));
}
__device__ __forceinline__ u32 packbf(float x, float y) {
    __nv_bfloat16 bx = __float2bfloat16(x), by = __float2bfloat16(y);
    return (u32)__bfloat16_as_ushort(bx) | ((u32)__bfloat16_as_ushort(by) << 16);
}

// ---------------- scratch (device globals; BSS zero-init; padding never written) ----------
__device__ float g_xin[B_ * KIN_PAD];
__device__ float g_scale1[DENSE_N];
__device__ float g_shift1[DENSE_N];
__device__ float g_sc1[NC_ * 256], g_sh1[NC_ * 256];
__device__ float g_sc2[NC_ * 128], g_sh2[NC_ * 128];
// bf16 hi/lo activation planes (padded spatially; pad stays zero)
__device__ __nv_bfloat16 g_x0h[B_ * 11 * 11 * 306], g_x0l[B_ * 11 * 11 * 306];
__device__ __nv_bfloat16 g_h1h[B_ * 9 * 9 * 256],   g_h1l[B_ * 9 * 9 * 256];
__device__ float g_h2[B_ * 16 * 16 * 128];
// transposed + split weights: W1 [c][co(256)][7680], W2 [c][par][co(128)][2304]
__device__ __nv_bfloat16 g_W1h[NC_ * 256 * 7680], g_W1l[NC_ * 256 * 7680];
__device__ __nv_bfloat16 g_W2h[NC_ * 4 * 128 * 2304], g_W2l[NC_ * 4 * 128 * 2304];
__device__ int g_order[B_];
__device__ int g_cstart[NC_ + 1];
__device__ int g_aoff1[7680];
__device__ int g_aoff2[4 * 2304];
__device__ int g_wrow2[4 * 2304];

// ---------------- per-class bucketing (deterministic, stable) ----------------------------
__global__ void k_classify(const int* __restrict__ labels) {
    __shared__ int slab[B_];
    __shared__ int spre[NC_ + 1];
    int t = threadIdx.x;
    slab[t] = labels[t];
    __syncthreads();
    int c = slab[t];
    int rank = 0;
    for (int j = 0; j < t; j++) rank += (slab[j] == c) ? 1 : 0;
    if (t == 0) {
        int cnt[NC_];
        for (int i = 0; i < NC_; i++) cnt[i] = 0;
        for (int j = 0; j < B_; j++) cnt[slab[j]]++;
        int acc = 0;
        for (int i = 0; i < NC_; i++) { spre[i] = acc; g_cstart[i] = acc; acc += cnt[i]; }
        spre[NC_] = acc; g_cstart[NC_] = acc;
    }
    __syncthreads();
    g_order[spre[c] + rank] = t;
}

// ---------------- dense input concat ----------------------------------------------------
__global__ void k_xin(const float* __restrict__ noise, const float* __restrict__ emb,
                      const int* __restrict__ labels) {
    int idx = blockIdx.x * blockDim.x + threadIdx.x;
    if (idx >= B_ * KIN) return;
    int b = idx / KIN, k = idx - b * KIN;
    float v = (k < NOISE_) ? noise[b * NOISE_ + k]
                           : emb[labels[b] * EMB_ + (k - NOISE_)];
    g_xin[b * KIN_PAD + k] = v;
}

// ---------------- BN folds ----------------------------------------------------------------
__global__ void k_bnscale1(const float* __restrict__ g, const float* __restrict__ bb,
                           const float* __restrict__ m, const float* __restrict__ v) {
    int i = blockIdx.x * blockDim.x + threadIdx.x;
    if (i >= DENSE_N) return;
    float s = g[i] * rsqrtf(v[i] + EPSBN);
    g_scale1[i] = s;
    g_shift1[i] = bb[i] - m[i] * s;
}

__global__ void k_bnbranch(const float* __restrict__ G1, const float* __restrict__ Bb1,
                           const float* __restrict__ M1, const float* __restrict__ V1,
                           const float* __restrict__ G2, const float* __restrict__ Bb2,
                           const float* __restrict__ M2, const float* __restrict__ V2) {
    int i = blockIdx.x * blockDim.x + threadIdx.x;
    if (i < NC_ * 256) {
        float s = G1[i] * rsqrtf(V1[i] + EPSBN);
        g_sc1[i] = s; g_sh1[i] = Bb1[i] - M1[i] * s;
    } else if (i < NC_ * 256 + NC_ * 128) {
        int j = i - NC_ * 256;
        float s = G2[j] * rsqrtf(V2[j] + EPSBN);
        g_sc2[j] = s; g_sh2[j] = Bb2[j] - M2[j] * s;
    }
}

// ---------------- gather/weight-row tables ------------------------------------------------
__global__ void k_tables() {
    int i = blockIdx.x * blockDim.x + threadIdx.x;
    if (i < 7680) {
        if (i < 7650) {
            int kh = i / 1530, r = i - kh * 1530, kw = r / 306, ci = r - kw * 306;
            g_aoff1[i] = (kh * 11 + kw) * 306 + ci;
        } else g_aoff1[i] = 0;   // pad; weight pad rows are zero so value is irrelevant
    } else if (i < 7680 + 4 * 2304) {
        int i2 = i - 7680;
        int par = i2 / 2304, q = i2 - par * 2304;
        int a = par >> 1, pb = par & 1;
        int nh = a ? 3 : 2, nw = pb ? 3 : 2;
        int Kp = nh * nw * 256;
        if (q < Kp) {
            int th = q / (nw * 256);
            int r = q - th * (nw * 256);
            int tw = r / 256, ci = r & 255;
            int kh = 2 * th + (a ? 0 : 1);
            int kw = 2 * tw + (pb ? 0 : 1);
            g_aoff2[par * 2304 + q] = (th * 9 + tw) * 256 + ci;
            g_wrow2[par * 2304 + q] = (kh * 5 + kw) * 256 + ci;
        }
    }
}

// ---------------- weight transpose + hi/lo split -----------------------------------------
// K1 [c][tap(25)][ci(306)][co(256)] -> W1 [c][co][k=tap*306+ci] (Kpad 7680, pad zero)
__global__ void k_wsplit1(const float* __restrict__ K1) {
    __shared__ float s[64][33];
    int cot = blockIdx.x, kt = blockIdx.y, c = blockIdx.z;
    int tid = threadIdx.x;
#pragma unroll
    for (int l = 0; l < 8; l++) {
        int idx = tid + l * 256;
        int kk = idx >> 5, coI = idx & 31;
        int k = kt * 64 + kk;
        float v = 0.f;
        if (k < 7650) {
            int tap = k / 306, ci = k - tap * 306;
            v = K1[((size_t)(c * 25 + tap) * 306 + ci) * 256 + cot * 32 + coI];
        }
        s[kk][coI] = v;
    }
    __syncthreads();
#pragma unroll
    for (int l = 0; l < 8; l++) {
        int idx = tid + l * 256;
        int co2 = idx >> 6, k2 = idx & 63;
        float v = s[k2][co2];
        __nv_bfloat16 hi = __float2bfloat16(v);
        __nv_bfloat16 lo = __float2bfloat16(v - __bfloat162float(hi));
        size_t o = ((size_t)(c * 256 + cot * 32 + co2)) * 7680 + kt * 64 + k2;
        g_W1h[o] = hi; g_W1l[o] = lo;
    }
}

// K2 [c][25*256][128] -> W2 [c][par][co][kp] via wrow2 (Kpad 2304 per parity, pad zero)
__global__ void k_wsplit2(const float* __restrict__ K2) {
    __shared__ float s[64][33];
    int par = blockIdx.x >> 2, cot = blockIdx.x & 3;
    int kt = blockIdx.y, c = blockIdx.z;
    int Kp = (2 + (par >> 1)) * (2 + (par & 1)) * 256;
    int tid = threadIdx.x;
#pragma unroll
    for (int l = 0; l < 8; l++) {
        int idx = tid + l * 256;
        int kk = idx >> 5, coI = idx & 31;
        int k = kt * 64 + kk;
        float v = 0.f;
        if (k < Kp) {
            int row = g_wrow2[par * 2304 + k];
            v = K2[((size_t)c * 6400 + row) * 128 + cot * 32 + coI];
        }
        s[kk][coI] = v;
    }
    __syncthreads();
#pragma unroll
    for (int l = 0; l < 8; l++) {
        int idx = tid + l * 256;
        int co2 = idx >> 6, k2 = idx & 63;
        float v = s[k2][co2];
        __nv_bfloat16 hi = __float2bfloat16(v);
        __nv_bfloat16 lo = __float2bfloat16(v - __bfloat162float(hi));
        size_t o = ((size_t)((c * 4 + par) * 128 + cot * 32 + co2)) * 2304 + kt * 64 + k2;
        g_W2h[o] = hi; g_W2l[o] = lo;
    }
}

// ---------------- dense GEMM + bn + lrelu -> x0 hi/lo bf16 -------------------------------
__global__ __launch_bounds__(256) void k_dense(const float* __restrict__ Wd) {
    __shared__ float As[2][TK][TM + 4];
    __shared__ float Bs[2][TK][TN];
    int tid = threadIdx.x, tx = tid & 15, ty = tid >> 4;
    int row0 = blockIdx.y * TM;
    int col0 = blockIdx.x * TN;
    int ar = tid >> 2, ak = (tid & 3) * 4;
    int bkk = tid >> 4, bn = (tid & 15) * 4;
    const float* arow = g_xin + (size_t)(row0 + ar) * KIN_PAD;

    u64 acc[4][2];
#pragma unroll
    for (int i = 0; i < 4; i++) { acc[i][0] = 0ull; acc[i][1] = 0ull; }

    const int nT = KIN_PAD / TK;
    float a_reg[4]; float4 b_reg;
    {
#pragma unroll
        for (int i = 0; i < 4; i++) a_reg[i] = arow[ak + i];
        int k = bkk;
        b_reg = (k < KIN) ? *(const float4*)(Wd + (size_t)k * DENSE_N + col0 + bn)
                          : make_float4(0.f, 0.f, 0.f, 0.f);
    }
    int buf = 0;
    for (int t = 0; t < nT; t++) {
#pragma unroll
        for (int i = 0; i < 4; i++) As[buf][ak + i][ar] = a_reg[i];
        *(float4*)&Bs[buf][bkk][bn] = b_reg;
        __syncthreads();
        if (t + 1 < nT) {
            int k0 = (t + 1) * TK;
#pragma unroll
            for (int i = 0; i < 4; i++) a_reg[i] = arow[k0 + ak + i];
            int k = k0 + bkk;
            b_reg = (k < KIN) ? *(const float4*)(Wd + (size_t)k * DENSE_N + col0 + bn)
                              : make_float4(0.f, 0.f, 0.f, 0.f);
        }
#pragma unroll
        for (int kk = 0; kk < TK; kk++) {
            float4 av = *(const float4*)&As[buf][kk][ty * 4];
            u64 b0 = *(const u64*)&Bs[buf][kk][tx * 4];
            u64 b1 = *(const u64*)&Bs[buf][kk][tx * 4 + 2];
            float aa[4] = {av.x, av.y, av.z, av.w};
#pragma unroll
            for (int i = 0; i < 4; i++) {
                u64 ad = pk2(aa[i], aa[i]);
                acc[i][0] = ffma2(ad, b0, acc[i][0]);
                acc[i][1] = ffma2(ad, b1, acc[i][1]);
            }
        }
        __syncthreads();
        buf ^= 1;
    }
#pragma unroll
    for (int i = 0; i < 4; i++) {
        int b = row0 + ty * 4 + i;
        float y4[4];
        upk2(acc[i][0], y4[0], y4[1]);
        upk2(acc[i][1], y4[2], y4[3]);
        int jc0 = col0 + tx * 4;
#pragma unroll
        for (int j = 0; j < 4; j++) {
            int jc = jc0 + j;
            float y = y4[j] * g_scale1[jc] + g_shift1[jc];
            y4[j] = (y >= 0.f) ? y : ALPHA * y;
        }
        int h = jc0 / 1792;
        int w = (jc0 >> 8) % 7;
        int ch = jc0 & 255;
        size_t xb = ((size_t)(b * 11 + h + 2) * 11 + (w + 2)) * 306 + ch;
        float hi0 = __bfloat162float(__float2bfloat16(y4[0]));
        float hi1 = __bfloat162float(__float2bfloat16(y4[1]));
        float hi2 = __bfloat162float(__float2bfloat16(y4[2]));
        float hi3 = __bfloat162float(__float2bfloat16(y4[3]));
        *(u32*)&g_x0h[xb]     = packbf(y4[0], y4[1]);
        *(u32*)&g_x0h[xb + 2] = packbf(y4[2], y4[3]);
        *(u32*)&g_x0l[xb]     = packbf(y4[0] - hi0, y4[1] - hi1);
        *(u32*)&g_x0l[xb + 2] = packbf(y4[2] - hi2, y4[3] - hi3);
    }
}

// ---------------- embedding channels 256..305 into x0 hi/lo ------------------------------
__global__ void k_embx0(const float* __restrict__ emb, const int* __restrict__ labels) {
    int idx = blockIdx.x * blockDim.x + threadIdx.x;
    if (idx >= B_ * 49 * EMB_) return;
    int e = idx % EMB_;
    int rest = idx / EMB_;
    int pos = rest % 49, b = rest / 49;
    int h = pos / 7, w = pos - h * 7;
    float v = emb[labels[b] * EMB_ + e];
    size_t o = ((size_t)(b * 11 + h + 2) * 11 + (w + 2)) * 306 + 256 + e;
    __nv_bfloat16 hi = __float2bfloat16(v);
    g_x0h[o] = hi;
    g_x0l[o] = __float2bfloat16(v - __bfloat162float(hi));
}

// ---------------- class-routed bf16 tensor-core gather-GEMM ------------------------------
// 3 passes: A_hi*B_hi + A_lo*B_hi + A_hi*B_lo  (fp32 accum; ~16-bit effective mantissa)
// mode 0: ConvT1 (blockIdx.x = col tile of 256); mode 1: ConvT2 (blockIdx.x = parity)
__global__ __launch_bounds__(256, 2) void k_mma(int mode) {
    __shared__ __nv_bfloat16 As[2][128 * PIT];
    __shared__ __nv_bfloat16 Bs[2][128 * PIT];

    int c = blockIdx.z;
    int s0 = g_cstart[c];
    int rows = (g_cstart[c + 1] - s0) * 49;
    int row0 = blockIdx.y * 128;
    if (row0 >= rows) return;

    const __nv_bfloat16 *Ah, *Al, *BhBase, *BlBase;
    const int* aoff;
    int K, N, Wstride, col0;
    int a_bs, a_pw, a_pc;
    const float *sc, *sh;
    int o_bs, o_rs, o_h0, o_hs, o_w0, o_ws;
    if (mode == 0) {
        Ah = g_x0h; Al = g_x0l;
        col0 = blockIdx.x * 128;
        BhBase = g_W1h + (size_t)(c * 256 + col0) * 7680;
        BlBase = g_W1l + (size_t)(c * 256 + col0) * 7680;
        Wstride = 7680; aoff = g_aoff1; K = 7680; N = 256;
        a_bs = 121 * 306; a_pw = 11; a_pc = 306;
        sc = g_sc1 + c * 256; sh = g_sh1 + c * 256;
        o_bs = 81 * 256; o_rs = 9 * 256; o_h0 = 1; o_hs = 1; o_w0 = 1; o_ws = 1;
    } else {
        int par = blockIdx.x;
        Ah = g_h1h; Al = g_h1l;
        col0 = 0;
        BhBase = g_W2h + (size_t)((c * 4 + par) * 128) * 2304;
        BlBase = g_W2l + (size_t)((c * 4 + par) * 128) * 2304;
        Wstride = 2304; aoff = g_aoff2 + par * 2304;
        K = (2 + (par >> 1)) * (2 + (par & 1)) * 256; N = 128;
        a_bs = 81 * 256; a_pw = 9; a_pc = 256;
        sc = g_sc2 + c * 128; sh = g_sh2 + c * 128;
        o_bs = 256 * 128; o_rs = 16 * 128;
        o_h0 = (par >> 1) + 1; o_hs = 2; o_w0 = (par & 1) + 1; o_ws = 2;
    }

    int tid = threadIdx.x;
    // fill assignments
    int fr = tid >> 1, fk = (tid & 1) * 16;          // A: row fr, k half
    int bnr = tid >> 1, bo = (tid & 1) * 16;         // B: n row, k half
    int a_idx = -1;
    {
        int r = row0 + fr;
        if (r < rows) {
            int sl = r / 49, pos = r - sl * 49;
            int b = g_order[s0 + sl];
            int h = pos / 7, w = pos - h * 7;
            a_idx = b * a_bs + (h * a_pw + w) * a_pc;
        }
    }
    // warp / fragment ids
    int wid = tid >> 5, lane = tid & 31;
    int g = lane >> 2, tg = lane & 3;
    int wm = (wid >> 2) * 64, wn = (wid & 3) * 32;

    float acc[4][4][4];
#pragma unroll
    for (int mi = 0; mi < 4; mi++)
#pragma unroll
        for (int ni = 0; ni < 4; ni++)
#pragma unroll
            for (int q = 0; q < 4; q++) acc[mi][ni][q] = 0.f;

    int nT = K / 32;
    int buf = 0;
    u32 pa[8]; uint4 pb0, pb1;

    for (int p = 0; p < 3; p++) {
        const __nv_bfloat16* Ap = (p == 1) ? Al : Ah;
        const __nv_bfloat16* Brow = ((p == 2) ? BlBase : BhBase) + (size_t)bnr * Wstride + bo;
        // prefetch tile 0
#pragma unroll
        for (int j = 0; j < 8; j++)
            pa[j] = (a_idx >= 0) ? *(const u32*)(Ap + a_idx + aoff[fk + 2 * j]) : 0u;
        pb0 = *(const uint4*)(Brow);
        pb1 = *(const uint4*)(Brow + 8);

        for (int t = 0; t < nT; t++) {
#pragma unroll
            for (int j = 0; j < 8; j++)
                *(u32*)&As[buf][fr * PIT + fk + 2 * j] = pa[j];
            *(uint4*)&Bs[buf][bnr * PIT + bo] = pb0;
            *(uint4*)&Bs[buf][bnr * PIT + bo + 8] = pb1;
            __syncthreads();
            if (t + 1 < nT) {
                int k0 = (t + 1) * 32;
#pragma unroll
                for (int j = 0; j < 8; j++)
                    pa[j] = (a_idx >= 0) ? *(const u32*)(Ap + a_idx + aoff[k0 + fk + 2 * j]) : 0u;
                pb0 = *(const uint4*)(Brow + k0);
                pb1 = *(const uint4*)(Brow + k0 + 8);
            }
#pragma unroll
            for (int ks = 0; ks < 2; ks++) {
                int kb = ks * 16;
                u32 bf[4][2];
#pragma unroll
                for (int ni = 0; ni < 4; ni++) {
                    const __nv_bfloat16* bp = &Bs[buf][(wn + ni * 8 + g) * PIT + kb + tg * 2];
                    bf[ni][0] = *(const u32*)bp;
                    bf[ni][1] = *(const u32*)(bp + 8);
                }
#pragma unroll
                for (int mi = 0; mi < 4; mi++) {
                    const __nv_bfloat16* ap = &As[buf][(wm + mi * 16 + g) * PIT + kb + tg * 2];
                    u32 a0 = *(const u32*)ap;
                    u32 a1 = *(const u32*)(ap + 8 * PIT);
                    u32 a2 = *(const u32*)(ap + 8);
                    u32 a3 = *(const u32*)(ap + 8 * PIT + 8);
#pragma unroll
                    for (int ni = 0; ni < 4; ni++)
                        mma16816(acc[mi][ni], a0, a1, a2, a3, bf[ni][0], bf[ni][1]);
                }
            }
            __syncthreads();
            buf ^= 1;
        }
    }

    // epilogue: bn + lrelu; mode0 -> h1 hi/lo bf16, mode1 -> h2 fp32
#pragma unroll
    for (int mi = 0; mi < 4; mi++) {
#pragma unroll
        for (int hh = 0; hh < 2; hh++) {
            int lr = wm + mi * 16 + g + hh * 8;
            int r = row0 + lr;
            if (r >= rows) continue;
            int sl = r / 49, pos = r - sl * 49;
            int b = g_order[s0 + sl];
            int h = pos / 7, w = pos - h * 7;
            size_t ob = (size_t)b * o_bs + (size_t)(o_h0 + h * o_hs) * o_rs
                      + (size_t)(o_w0 + w * o_ws) * (size_t)N;
#pragma unroll
            for (int ni = 0; ni < 4; ni++) {
                int co = wn + ni * 8 + tg * 2;
                int gco = col0 + co;
                float v0 = acc[mi][ni][hh * 2 + 0];
                float v1 = acc[mi][ni][hh * 2 + 1];
                v0 = v0 * sc[gco] + sh[gco];
                v1 = v1 * sc[gco + 1] + sh[gco + 1];
                v0 = (v0 >= 0.f) ? v0 : ALPHA * v0;
                v1 = (v1 >= 0.f) ? v1 : ALPHA * v1;
                if (mode == 0) {
                    float h0 = __bfloat162float(__float2bfloat16(v0));
                    float h1 = __bfloat162float(__float2bfloat16(v1));
                    *(u32*)&g_h1h[ob + gco] = packbf(v0, v1);
                    *(u32*)&g_h1l[ob + gco] = packbf(v0 - h0, v1 - h1);
                } else {
                    *(float2*)&g_h2[ob + gco] = make_float2(v0, v1);
                }
            }
        }
    }
}

// ---------------- ConvT3 (N=1) + tanh ----------------------------------------------------
__global__ __launch_bounds__(256) void k_convt3(const float* __restrict__ K3,
                                                const int* __restrict__ labels,
                                                float* __restrict__ out) {
    int b = blockIdx.x;
    int c = labels[b];
    __shared__ float Ks[5 * 5 * 128];
    for (int i = threadIdx.x; i < 5 * 5 * 128; i += blockDim.x)
        Ks[i] = K3[c * (5 * 5 * 128) + i];
    __syncthreads();
    const float* hb = g_h2 + (size_t)b * 16 * 16 * 128;
    for (int p = threadIdx.x; p < 784; p += blockDim.x) {
        int oh = p / 28, ow = p - oh * 28;
        int i = oh >> 1, a = oh & 1, j = ow >> 1, pb = ow & 1;
        int nh = a ? 3 : 2, nw = pb ? 3 : 2;
        float acc = 0.f;
        for (int th = 0; th < nh; th++) {
            int kh = 2 * th + (a ? 0 : 1);
            int ph = i + th;
            for (int tw = 0; tw < nw; tw++) {
                int kw = 2 * tw + (pb ? 0 : 1);
                int pw = j + tw;
                const float* xp = hb + (size_t)(ph * 16 + pw) * 128;
                const float* wp = Ks + (kh * 5 + kw) * 128;
#pragma unroll
                for (int ci = 0; ci < 128; ci += 4) {
                    float4 xv = *(const float4*)(xp + ci);
                    float4 wv = *(const float4*)(wp + ci);
                    acc += xv.x * wv.x + xv.y * wv.y + xv.z * wv.z + xv.w * wv.w;
                }
            }
        }
        out[(size_t)b * 784 + p] = tanhf(acc);
    }
}

// ---------------- launch ----------------------------------------------------------------
extern "C" void kernel_launch(void* const* d_in, const int* in_sizes, int n_in,
                              void* d_out, int out_size) {
    const float* noise = (const float*)d_in[0];
    const int*   labels = (const int*)d_in[1];
    const float* emb  = (const float*)d_in[2];
    const float* Wd   = (const float*)d_in[3];
    const float* bn1_g = (const float*)d_in[4];
    const float* bn1_b = (const float*)d_in[5];
    const float* bn1_m = (const float*)d_in[6];
    const float* bn1_v = (const float*)d_in[7];
    const float* K1 = (const float*)d_in[8];
    const float* G1 = (const float*)d_in[9];
    const float* B1 = (const float*)d_in[10];
    const float* M1 = (const float*)d_in[11];
    const float* V1 = (const float*)d_in[12];
    const float* K2 = (const float*)d_in[13];
    const float* G2 = (const float*)d_in[14];
    const float* B2 = (const float*)d_in[15];
    const float* M2 = (const float*)d_in[16];
    const float* V2 = (const float*)d_in[17];
    const float* K3 = (const float*)d_in[18];
    float* out = (float*)d_out;

    k_classify<<<1, B_>>>(labels);
    k_xin<<<(B_ * KIN + 255) / 256, 256>>>(noise, emb, labels);
    k_bnscale1<<<(DENSE_N + 255) / 256, 256>>>(bn1_g, bn1_b, bn1_m, bn1_v);
    k_bnbranch<<<(NC_ * 256 + NC_ * 128 + 255) / 256, 256>>>(G1, B1, M1, V1, G2, B2, M2, V2);
    k_tables<<<(7680 + 4 * 2304 + 255) / 256, 256>>>();

    // weight transpose + bf16 hi/lo split
    k_wsplit1<<<dim3(8, 120, NC_), 256>>>(K1);
    k_wsplit2<<<dim3(16, 36, NC_), 256>>>(K2);

    k_dense<<<dim3(DENSE_N / TN, B_ / TM), 256>>>(Wd);
    k_embx0<<<(B_ * 49 * EMB_ + 255) / 256, 256>>>(emb, labels);

    // ConvT1: 2 col tiles x row tiles x classes (empty tiles exit)
    k_mma<<<dim3(2, (B_ * 49 + 127) / 128, NC_), 256>>>(0);
    // ConvT2: 4 parities x row tiles x classes
    k_mma<<<dim3(4, (B_ * 49 + 127) / 128, NC_), 256>>>(1);

    k_convt3<<<B_, 256>>>(K3, labels, out);
    (void)in_sizes; (void)n_in; (void)out_size;
}

// round 8
// speedup vs baseline: 1.2919x; 1.0745x over previous
#include <cuda_runtime.h>
#include <cuda_bf16.h>

#define ALPHA 0.3f
#define EPSBN 1e-3f

#define B_ 512
#define NOISE_ 100
#define NC_ 10
#define EMB_ 50
#define DENSE_N 12544   /* 7*7*256 */
#define KIN 150
#define KIN_PAD 160

/* dense GEMM tile */
#define TM 64
#define TN 64
#define TK 16

/* mma smem pitch (bf16 elems per row) */
#define PIT 40

typedef unsigned int u32;
typedef unsigned long long u64;

__device__ __forceinline__ u64 pk2(float lo, float hi) {
    u64 r; asm("mov.b64 %0, {%1, %2};" : "=l"(r) : "f"(lo), "f"(hi)); return r;
}
__device__ __forceinline__ u64 ffma2(u64 a, u64 b, u64 c) {
    u64 d; asm("fma.rn.f32x2 %0, %1, %2, %3;" : "=l"(d) : "l"(a), "l"(b), "l"(c)); return d;
}
__device__ __forceinline__ void upk2(u64 v, float& lo, float& hi) {
    asm("mov.b64 {%0, %1}, %2;" : "=f"(lo), "=f"(hi) : "l"(v));
}
__device__ __forceinline__ void mma16816(float* c, u32 a0, u32 a1, u32 a2, u32 a3,
                                         u32 b0, u32 b1) {
    asm volatile("mma.sync.aligned.m16n8k16.row.col.f32.bf16.bf16.f32 "
                 "{%0,%1,%2,%3}, {%4,%5,%6,%7}, {%8,%9}, {%0,%1,%2,%3};"
                 : "+f"(c[0]), "+f"(c[1]), "+f"(c[2]), "+f"(c[3])
                 : "r"(a0), "r"(a1), "r"(a2), "r"(a3), "r"(b0), "r"(b1));
}
__device__ __forceinline__ u32 packbf(float x, float y) {
    __nv_bfloat16 bx = __float2bfloat16(x), by = __float2bfloat16(y);
    return (u32)__bfloat16_as_ushort(bx) | ((u32)__bfloat16_as_ushort(by) << 16);
}

// ---------------- scratch (device globals; BSS zero-init; padding never written) ----------
__device__ float g_xin[B_ * KIN_PAD];
__device__ float g_scale1[DENSE_N];
__device__ float g_shift1[DENSE_N];
__device__ float g_sc1[NC_ * 256], g_sh1[NC_ * 256];
__device__ float g_sc2[NC_ * 128], g_sh2[NC_ * 128];
__device__ __nv_bfloat16 g_x0h[B_ * 11 * 11 * 306], g_x0l[B_ * 11 * 11 * 306];
__device__ __nv_bfloat16 g_h1h[B_ * 9 * 9 * 256],   g_h1l[B_ * 9 * 9 * 256];
__device__ float g_h2[B_ * 16 * 16 * 128];
__device__ __nv_bfloat16 g_W1h[NC_ * 256 * 7680], g_W1l[NC_ * 256 * 7680];
__device__ __nv_bfloat16 g_W2h[NC_ * 4 * 128 * 2304], g_W2l[NC_ * 4 * 128 * 2304];
__device__ int g_order[B_];
__device__ int g_cstart[NC_ + 1];
__device__ int g_aoff1[7680];
__device__ int g_aoff2[4 * 2304];
__device__ int g_wrow2[4 * 2304];

// ---------------- per-class bucketing -----------------------------------------------------
__global__ void k_classify(const int* __restrict__ labels) {
    __shared__ int slab[B_];
    __shared__ int spre[NC_ + 1];
    int t = threadIdx.x;
    slab[t] = labels[t];
    __syncthreads();
    int c = slab[t];
    int rank = 0;
    for (int j = 0; j < t; j++) rank += (slab[j] == c) ? 1 : 0;
    if (t == 0) {
        int cnt[NC_];
        for (int i = 0; i < NC_; i++) cnt[i] = 0;
        for (int j = 0; j < B_; j++) cnt[slab[j]]++;
        int acc = 0;
        for (int i = 0; i < NC_; i++) { spre[i] = acc; g_cstart[i] = acc; acc += cnt[i]; }
        spre[NC_] = acc; g_cstart[NC_] = acc;
    }
    __syncthreads();
    g_order[spre[c] + rank] = t;
}

// ---------------- dense input concat ----------------------------------------------------
__global__ void k_xin(const float* __restrict__ noise, const float* __restrict__ emb,
                      const int* __restrict__ labels) {
    int idx = blockIdx.x * blockDim.x + threadIdx.x;
    if (idx >= B_ * KIN) return;
    int b = idx / KIN, k = idx - b * KIN;
    float v = (k < NOISE_) ? noise[b * NOISE_ + k]
                           : emb[labels[b] * EMB_ + (k - NOISE_)];
    g_xin[b * KIN_PAD + k] = v;
}

// ---------------- BN folds ----------------------------------------------------------------
__global__ void k_bnscale1(const float* __restrict__ g, const float* __restrict__ bb,
                           const float* __restrict__ m, const float* __restrict__ v) {
    int i = blockIdx.x * blockDim.x + threadIdx.x;
    if (i >= DENSE_N) return;
    float s = g[i] * rsqrtf(v[i] + EPSBN);
    g_scale1[i] = s;
    g_shift1[i] = bb[i] - m[i] * s;
}

__global__ void k_bnbranch(const float* __restrict__ G1, const float* __restrict__ Bb1,
                           const float* __restrict__ M1, const float* __restrict__ V1,
                           const float* __restrict__ G2, const float* __restrict__ Bb2,
                           const float* __restrict__ M2, const float* __restrict__ V2) {
    int i = blockIdx.x * blockDim.x + threadIdx.x;
    if (i < NC_ * 256) {
        float s = G1[i] * rsqrtf(V1[i] + EPSBN);
        g_sc1[i] = s; g_sh1[i] = Bb1[i] - M1[i] * s;
    } else if (i < NC_ * 256 + NC_ * 128) {
        int j = i - NC_ * 256;
        float s = G2[j] * rsqrtf(V2[j] + EPSBN);
        g_sc2[j] = s; g_sh2[j] = Bb2[j] - M2[j] * s;
    }
}

// ---------------- gather/weight-row tables ------------------------------------------------
__global__ void k_tables() {
    int i = blockIdx.x * blockDim.x + threadIdx.x;
    if (i < 7680) {
        if (i < 7650) {
            int kh = i / 1530, r = i - kh * 1530, kw = r / 306, ci = r - kw * 306;
            g_aoff1[i] = (kh * 11 + kw) * 306 + ci;
        } else g_aoff1[i] = 0;
    } else if (i < 7680 + 4 * 2304) {
        int i2 = i - 7680;
        int par = i2 / 2304, q = i2 - par * 2304;
        int a = par >> 1, pb = par & 1;
        int nh = a ? 3 : 2, nw = pb ? 3 : 2;
        int Kp = nh * nw * 256;
        if (q < Kp) {
            int th = q / (nw * 256);
            int r = q - th * (nw * 256);
            int tw = r / 256, ci = r & 255;
            int kh = 2 * th + (a ? 0 : 1);
            int kw = 2 * tw + (pb ? 0 : 1);
            g_aoff2[par * 2304 + q] = (th * 9 + tw) * 256 + ci;
            g_wrow2[par * 2304 + q] = (kh * 5 + kw) * 256 + ci;
        }
    }
}

// ---------------- weight transpose + hi/lo split -----------------------------------------
__global__ void k_wsplit1(const float* __restrict__ K1) {
    __shared__ float s[64][33];
    int cot = blockIdx.x, kt = blockIdx.y, c = blockIdx.z;
    int tid = threadIdx.x;
#pragma unroll
    for (int l = 0; l < 8; l++) {
        int idx = tid + l * 256;
        int kk = idx >> 5, coI = idx & 31;
        int k = kt * 64 + kk;
        float v = 0.f;
        if (k < 7650) {
            int tap = k / 306, ci = k - tap * 306;
            v = K1[((size_t)(c * 25 + tap) * 306 + ci) * 256 + cot * 32 + coI];
        }
        s[kk][coI] = v;
    }
    __syncthreads();
#pragma unroll
    for (int l = 0; l < 8; l++) {
        int idx = tid + l * 256;
        int co2 = idx >> 6, k2 = idx & 63;
        float v = s[k2][co2];
        __nv_bfloat16 hi = __float2bfloat16(v);
        __nv_bfloat16 lo = __float2bfloat16(v - __bfloat162float(hi));
        size_t o = ((size_t)(c * 256 + cot * 32 + co2)) * 7680 + kt * 64 + k2;
        g_W1h[o] = hi; g_W1l[o] = lo;
    }
}

__global__ void k_wsplit2(const float* __restrict__ K2) {
    __shared__ float s[64][33];
    int par = blockIdx.x >> 2, cot = blockIdx.x & 3;
    int kt = blockIdx.y, c = blockIdx.z;
    int Kp = (2 + (par >> 1)) * (2 + (par & 1)) * 256;
    int tid = threadIdx.x;
#pragma unroll
    for (int l = 0; l < 8; l++) {
        int idx = tid + l * 256;
        int kk = idx >> 5, coI = idx & 31;
        int k = kt * 64 + kk;
        float v = 0.f;
        if (k < Kp) {
            int row = g_wrow2[par * 2304 + k];
            v = K2[((size_t)c * 6400 + row) * 128 + cot * 32 + coI];
        }
        s[kk][coI] = v;
    }
    __syncthreads();
#pragma unroll
    for (int l = 0; l < 8; l++) {
        int idx = tid + l * 256;
        int co2 = idx >> 6, k2 = idx & 63;
        float v = s[k2][co2];
        __nv_bfloat16 hi = __float2bfloat16(v);
        __nv_bfloat16 lo = __float2bfloat16(v - __bfloat162float(hi));
        size_t o = ((size_t)((c * 4 + par) * 128 + cot * 32 + co2)) * 2304 + kt * 64 + k2;
        g_W2h[o] = hi; g_W2l[o] = lo;
    }
}

// ---------------- dense GEMM + bn + lrelu -> x0 hi/lo bf16 -------------------------------
__global__ __launch_bounds__(256) void k_dense(const float* __restrict__ Wd) {
    __shared__ float As[2][TK][TM + 4];
    __shared__ float Bs[2][TK][TN];
    int tid = threadIdx.x, tx = tid & 15, ty = tid >> 4;
    int row0 = blockIdx.y * TM;
    int col0 = blockIdx.x * TN;
    int ar = tid >> 2, ak = (tid & 3) * 4;
    int bkk = tid >> 4, bn = (tid & 15) * 4;
    const float* arow = g_xin + (size_t)(row0 + ar) * KIN_PAD;

    u64 acc[4][2];
#pragma unroll
    for (int i = 0; i < 4; i++) { acc[i][0] = 0ull; acc[i][1] = 0ull; }

    const int nT = KIN_PAD / TK;
    float a_reg[4]; float4 b_reg;
    {
#pragma unroll
        for (int i = 0; i < 4; i++) a_reg[i] = arow[ak + i];
        int k = bkk;
        b_reg = (k < KIN) ? *(const float4*)(Wd + (size_t)k * DENSE_N + col0 + bn)
                          : make_float4(0.f, 0.f, 0.f, 0.f);
    }
    int buf = 0;
    for (int t = 0; t < nT; t++) {
#pragma unroll
        for (int i = 0; i < 4; i++) As[buf][ak + i][ar] = a_reg[i];
        *(float4*)&Bs[buf][bkk][bn] = b_reg;
        __syncthreads();
        if (t + 1 < nT) {
            int k0 = (t + 1) * TK;
#pragma unroll
            for (int i = 0; i < 4; i++) a_reg[i] = arow[k0 + ak + i];
            int k = k0 + bkk;
            b_reg = (k < KIN) ? *(const float4*)(Wd + (size_t)k * DENSE_N + col0 + bn)
                              : make_float4(0.f, 0.f, 0.f, 0.f);
        }
#pragma unroll
        for (int kk = 0; kk < TK; kk++) {
            float4 av = *(const float4*)&As[buf][kk][ty * 4];
            u64 b0 = *(const u64*)&Bs[buf][kk][tx * 4];
            u64 b1 = *(const u64*)&Bs[buf][kk][tx * 4 + 2];
            float aa[4] = {av.x, av.y, av.z, av.w};
#pragma unroll
            for (int i = 0; i < 4; i++) {
                u64 ad = pk2(aa[i], aa[i]);
                acc[i][0] = ffma2(ad, b0, acc[i][0]);
                acc[i][1] = ffma2(ad, b1, acc[i][1]);
            }
        }
        __syncthreads();
        buf ^= 1;
    }
#pragma unroll
    for (int i = 0; i < 4; i++) {
        int b = row0 + ty * 4 + i;
        float y4[4];
        upk2(acc[i][0], y4[0], y4[1]);
        upk2(acc[i][1], y4[2], y4[3]);
        int jc0 = col0 + tx * 4;
#pragma unroll
        for (int j = 0; j < 4; j++) {
            int jc = jc0 + j;
            float y = y4[j] * g_scale1[jc] + g_shift1[jc];
            y4[j] = (y >= 0.f) ? y : ALPHA * y;
        }
        int h = jc0 / 1792;
        int w = (jc0 >> 8) % 7;
        int ch = jc0 & 255;
        size_t xb = ((size_t)(b * 11 + h + 2) * 11 + (w + 2)) * 306 + ch;
        float hi0 = __bfloat162float(__float2bfloat16(y4[0]));
        float hi1 = __bfloat162float(__float2bfloat16(y4[1]));
        float hi2 = __bfloat162float(__float2bfloat16(y4[2]));
        float hi3 = __bfloat162float(__float2bfloat16(y4[3]));
        *(u32*)&g_x0h[xb]     = packbf(y4[0], y4[1]);
        *(u32*)&g_x0h[xb + 2] = packbf(y4[2], y4[3]);
        *(u32*)&g_x0l[xb]     = packbf(y4[0] - hi0, y4[1] - hi1);
        *(u32*)&g_x0l[xb + 2] = packbf(y4[2] - hi2, y4[3] - hi3);
    }
}

// ---------------- embedding channels 256..305 into x0 hi/lo ------------------------------
__global__ void k_embx0(const float* __restrict__ emb, const int* __restrict__ labels) {
    int idx = blockIdx.x * blockDim.x + threadIdx.x;
    if (idx >= B_ * 49 * EMB_) return;
    int e = idx % EMB_;
    int rest = idx / EMB_;
    int pos = rest % 49, b = rest / 49;
    int h = pos / 7, w = pos - h * 7;
    float v = emb[labels[b] * EMB_ + e];
    size_t o = ((size_t)(b * 11 + h + 2) * 11 + (w + 2)) * 306 + 256 + e;
    __nv_bfloat16 hi = __float2bfloat16(v);
    g_x0h[o] = hi;
    g_x0l[o] = __float2bfloat16(v - __bfloat162float(hi));
}

// ---------------- class-routed bf16 tensor-core gather-GEMM ------------------------------
// 3 passes: A_hi*B_hi + A_lo*B_hi + A_hi*B_lo (fp32 accum)
// Coalesced fills: lanes k-contiguous within a row; per-row gather bases in smem.
__global__ __launch_bounds__(256, 2) void k_mma(int mode) {
    __shared__ __nv_bfloat16 As[2][128 * PIT];
    __shared__ __nv_bfloat16 Bs[2][128 * PIT];
    __shared__ int sAidx[128];

    int c = blockIdx.z;
    int s0 = g_cstart[c];
    int rows = (g_cstart[c + 1] - s0) * 49;
    int row0 = blockIdx.y * 128;
    if (row0 >= rows) return;

    const __nv_bfloat16 *Ah, *Al, *BhBase, *BlBase;
    const int* aoff;
    int K, N, Wstride, col0;
    int a_bs, a_pw, a_pc;
    const float *sc, *sh;
    int o_bs, o_rs, o_h0, o_hs, o_w0, o_ws;
    if (mode == 0) {
        Ah = g_x0h; Al = g_x0l;
        col0 = blockIdx.x * 128;
        BhBase = g_W1h + (size_t)(c * 256 + col0) * 7680;
        BlBase = g_W1l + (size_t)(c * 256 + col0) * 7680;
        Wstride = 7680; aoff = g_aoff1; K = 7680; N = 256;
        a_bs = 121 * 306; a_pw = 11; a_pc = 306;
        sc = g_sc1 + c * 256; sh = g_sh1 + c * 256;
        o_bs = 81 * 256; o_rs = 9 * 256; o_h0 = 1; o_hs = 1; o_w0 = 1; o_ws = 1;
    } else {
        int par = blockIdx.x;
        Ah = g_h1h; Al = g_h1l;
        col0 = 0;
        BhBase = g_W2h + (size_t)((c * 4 + par) * 128) * 2304;
        BlBase = g_W2l + (size_t)((c * 4 + par) * 128) * 2304;
        Wstride = 2304; aoff = g_aoff2 + par * 2304;
        K = (2 + (par >> 1)) * (2 + (par & 1)) * 256; N = 128;
        a_bs = 81 * 256; a_pw = 9; a_pc = 256;
        sc = g_sc2 + c * 128; sh = g_sh2 + c * 128;
        o_bs = 256 * 128; o_rs = 16 * 128;
        o_h0 = (par >> 1) + 1; o_hs = 2; o_w0 = (par & 1) + 1; o_ws = 2;
    }

    int tid = threadIdx.x;
    // per-row gather base table (loop-invariant)
    if (tid < 128) {
        int r = row0 + tid;
        int ai = -1;
        if (r < rows) {
            int sl = r / 49, pos = r - sl * 49;
            int b = g_order[s0 + sl];
            int h = pos / 7, w = pos - h * 7;
            ai = b * a_bs + (h * a_pw + w) * a_pc;
        }
        sAidx[tid] = ai;
    }
    __syncthreads();

    // fill assignments (coalesced: lanes sweep k within a row)
    int kq = (tid & 15) * 2;        // A: k pair within 32-slab
    int rA = tid >> 4;              // A: row base (16 rows/step, 8 steps)
    int bq = (tid & 3) * 8;         // B: 8-elem (16B) quarter of 32-slab
    int rB = tid >> 2;              // B: n row base (64 rows/step, 2 steps)
    int aidxA[8];
#pragma unroll
    for (int j = 0; j < 8; j++) aidxA[j] = sAidx[rA + j * 16];

    // warp / fragment ids
    int wid = tid >> 5, lane = tid & 31;
    int g = lane >> 2, tg = lane & 3;
    int wm = (wid >> 2) * 64, wn = (wid & 3) * 32;

    float acc[4][4][4];
#pragma unroll
    for (int mi = 0; mi < 4; mi++)
#pragma unroll
        for (int ni = 0; ni < 4; ni++)
#pragma unroll
            for (int q = 0; q < 4; q++) acc[mi][ni][q] = 0.f;

    int nT = K / 32;
    int buf = 0;
    u32 pa[8]; uint4 pb[2];

    for (int p = 0; p < 3; p++) {
        const __nv_bfloat16* Ap = (p == 1) ? Al : Ah;
        const __nv_bfloat16* Bp = (p == 2) ? BlBase : BhBase;
        // prefetch tile 0
        {
            int ao = aoff[kq];
#pragma unroll
            for (int j = 0; j < 8; j++)
                pa[j] = (aidxA[j] >= 0) ? *(const u32*)(Ap + aidxA[j] + ao) : 0u;
#pragma unroll
            for (int j = 0; j < 2; j++)
                pb[j] = *(const uint4*)(Bp + (size_t)(rB + j * 64) * Wstride + bq);
        }
        for (int t = 0; t < nT; t++) {
#pragma unroll
            for (int j = 0; j < 8; j++)
                *(u32*)&As[buf][(rA + j * 16) * PIT + kq] = pa[j];
#pragma unroll
            for (int j = 0; j < 2; j++)
                *(uint4*)&Bs[buf][(rB + j * 64) * PIT + bq] = pb[j];
            __syncthreads();
            if (t + 1 < nT) {
                int k0 = (t + 1) * 32;
                int ao = aoff[k0 + kq];
#pragma unroll
                for (int j = 0; j < 8; j++)
                    pa[j] = (aidxA[j] >= 0) ? *(const u32*)(Ap + aidxA[j] + ao) : 0u;
#pragma unroll
                for (int j = 0; j < 2; j++)
                    pb[j] = *(const uint4*)(Bp + (size_t)(rB + j * 64) * Wstride + k0 + bq);
            }
#pragma unroll
            for (int ks = 0; ks < 2; ks++) {
                int kb = ks * 16;
                u32 bf[4][2];
#pragma unroll
                for (int ni = 0; ni < 4; ni++) {
                    const __nv_bfloat16* bp = &Bs[buf][(wn + ni * 8 + g) * PIT + kb + tg * 2];
                    bf[ni][0] = *(const u32*)bp;
                    bf[ni][1] = *(const u32*)(bp + 8);
                }
#pragma unroll
                for (int mi = 0; mi < 4; mi++) {
                    const __nv_bfloat16* ap = &As[buf][(wm + mi * 16 + g) * PIT + kb + tg * 2];
                    u32 a0 = *(const u32*)ap;
                    u32 a1 = *(const u32*)(ap + 8 * PIT);
                    u32 a2 = *(const u32*)(ap + 8);
                    u32 a3 = *(const u32*)(ap + 8 * PIT + 8);
#pragma unroll
                    for (int ni = 0; ni < 4; ni++)
                        mma16816(acc[mi][ni], a0, a1, a2, a3, bf[ni][0], bf[ni][1]);
                }
            }
            __syncthreads();
            buf ^= 1;
        }
    }

    // epilogue: bn + lrelu; mode0 -> h1 hi/lo bf16, mode1 -> h2 fp32
#pragma unroll
    for (int mi = 0; mi < 4; mi++) {
#pragma unroll
        for (int hh = 0; hh < 2; hh++) {
            int lr = wm + mi * 16 + g + hh * 8;
            int r = row0 + lr;
            if (r >= rows) continue;
            int sl = r / 49, pos = r - sl * 49;
            int b = g_order[s0 + sl];
            int h = pos / 7, w = pos - h * 7;
            size_t ob = (size_t)b * o_bs + (size_t)(o_h0 + h * o_hs) * o_rs
                      + (size_t)(o_w0 + w * o_ws) * (size_t)N;
#pragma unroll
            for (int ni = 0; ni < 4; ni++) {
                int co = wn + ni * 8 + tg * 2;
                int gco = col0 + co;
                float v0 = acc[mi][ni][hh * 2 + 0];
                float v1 = acc[mi][ni][hh * 2 + 1];
                v0 = v0 * sc[gco] + sh[gco];
                v1 = v1 * sc[gco + 1] + sh[gco + 1];
                v0 = (v0 >= 0.f) ? v0 : ALPHA * v0;
                v1 = (v1 >= 0.f) ? v1 : ALPHA * v1;
                if (mode == 0) {
                    float h0 = __bfloat162float(__float2bfloat16(v0));
                    float h1 = __bfloat162float(__float2bfloat16(v1));
                    *(u32*)&g_h1h[ob + gco] = packbf(v0, v1);
                    *(u32*)&g_h1l[ob + gco] = packbf(v0 - h0, v1 - h1);
                } else {
                    *(float2*)&g_h2[ob + gco] = make_float2(v0, v1);
                }
            }
        }
    }
}

// ---------------- ConvT3 (N=1) + tanh ----------------------------------------------------
__global__ __launch_bounds__(256) void k_convt3(const float* __restrict__ K3,
                                                const int* __restrict__ labels,
                                                float* __restrict__ out) {
    int b = blockIdx.x;
    int c = labels[b];
    __shared__ float Ks[5 * 5 * 128];
    for (int i = threadIdx.x; i < 5 * 5 * 128; i += blockDim.x)
        Ks[i] = K3[c * (5 * 5 * 128) + i];
    __syncthreads();
    const float* hb = g_h2 + (size_t)b * 16 * 16 * 128;
    for (int p = threadIdx.x; p < 784; p += blockDim.x) {
        int oh = p / 28, ow = p - oh * 28;
        int i = oh >> 1, a = oh & 1, j = ow >> 1, pb = ow & 1;
        int nh = a ? 3 : 2, nw = pb ? 3 : 2;
        float acc = 0.f;
        for (int th = 0; th < nh; th++) {
            int kh = 2 * th + (a ? 0 : 1);
            int ph = i + th;
            for (int tw = 0; tw < nw; tw++) {
                int kw = 2 * tw + (pb ? 0 : 1);
                int pw = j + tw;
                const float* xp = hb + (size_t)(ph * 16 + pw) * 128;
                const float* wp = Ks + (kh * 5 + kw) * 128;
#pragma unroll
                for (int ci = 0; ci < 128; ci += 4) {
                    float4 xv = *(const float4*)(xp + ci);
                    float4 wv = *(const float4*)(wp + ci);
                    acc += xv.x * wv.x + xv.y * wv.y + xv.z * wv.z + xv.w * wv.w;
                }
            }
        }
        out[(size_t)b * 784 + p] = tanhf(acc);
    }
}

// ---------------- launch ----------------------------------------------------------------
extern "C" void kernel_launch(void* const* d_in, const int* in_sizes, int n_in,
                              void* d_out, int out_size) {
    const float* noise = (const float*)d_in[0];
    const int*   labels = (const int*)d_in[1];
    const float* emb  = (const float*)d_in[2];
    const float* Wd   = (const float*)d_in[3];
    const float* bn1_g = (const float*)d_in[4];
    const float* bn1_b = (const float*)d_in[5];
    const float* bn1_m = (const float*)d_in[6];
    const float* bn1_v = (const float*)d_in[7];
    const float* K1 = (const float*)d_in[8];
    const float* G1 = (const float*)d_in[9];
    const float* B1 = (const float*)d_in[10];
    const float* M1 = (const float*)d_in[11];
    const float* V1 = (const float*)d_in[12];
    const float* K2 = (const float*)d_in[13];
    const float* G2 = (const float*)d_in[14];
    const float* B2 = (const float*)d_in[15];
    const float* M2 = (const float*)d_in[16];
    const float* V2 = (const float*)d_in[17];
    const float* K3 = (const float*)d_in[18];
    float* out = (float*)d_out;

    k_classify<<<1, B_>>>(labels);
    k_xin<<<(B_ * KIN + 255) / 256, 256>>>(noise, emb, labels);
    k_bnscale1<<<(DENSE_N + 255) / 256, 256>>>(bn1_g, bn1_b, bn1_m, bn1_v);
    k_bnbranch<<<(NC_ * 256 + NC_ * 128 + 255) / 256, 256>>>(G1, B1, M1, V1, G2, B2, M2, V2);
    k_tables<<<(7680 + 4 * 2304 + 255) / 256, 256>>>();

    k_wsplit1<<<dim3(8, 120, NC_), 256>>>(K1);
    k_wsplit2<<<dim3(16, 36, NC_), 256>>>(K2);

    k_dense<<<dim3(DENSE_N / TN, B_ / TM), 256>>>(Wd);
    k_embx0<<<(B_ * 49 * EMB_ + 255) / 256, 256>>>(emb, labels);

    k_mma<<<dim3(2, (B_ * 49 + 127) / 128, NC_), 256>>>(0);
    k_mma<<<dim3(4, (B_ * 49 + 127) / 128, NC_), 256>>>(1);

    k_convt3<<<B_, 256>>>(K3, labels, out);
    (void)in_sizes; (void)n_in; (void)out_size;
}

// round 13
// speedup vs baseline: 2.1839x; 1.6904x over previous
#include <cuda_runtime.h>
#include <cuda_bf16.h>

#define ALPHA 0.3f
#define EPSBN 1e-3f

#define B_ 512
#define NOISE_ 100
#define NC_ 10
#define EMB_ 50
#define DENSE_N 12544   /* 7*7*256 */
#define KIN 150
#define KIN_PAD 160

/* dense GEMM tile */
#define TM 64
#define TN 64
#define TK 16

/* mma smem pitch (bf16 elems per 32-k slab row) */
#define PIT 40
#define PLANE (128 * PIT)

typedef unsigned int u32;
typedef unsigned long long u64;

__device__ __forceinline__ u64 pk2(float lo, float hi) {
    u64 r; asm("mov.b64 %0, {%1, %2};" : "=l"(r) : "f"(lo), "f"(hi)); return r;
}
__device__ __forceinline__ u64 ffma2(u64 a, u64 b, u64 c) {
    u64 d; asm("fma.rn.f32x2 %0, %1, %2, %3;" : "=l"(d) : "l"(a), "l"(b), "l"(c)); return d;
}
__device__ __forceinline__ void upk2(u64 v, float& lo, float& hi) {
    asm("mov.b64 {%0, %1}, %2;" : "=f"(lo), "=f"(hi) : "l"(v));
}
__device__ __forceinline__ void mma16816(float* c, u32 a0, u32 a1, u32 a2, u32 a3,
                                         u32 b0, u32 b1) {
    asm volatile("mma.sync.aligned.m16n8k16.row.col.f32.bf16.bf16.f32 "
                 "{%0,%1,%2,%3}, {%4,%5,%6,%7}, {%8,%9}, {%0,%1,%2,%3};"
                 : "+f"(c[0]), "+f"(c[1]), "+f"(c[2]), "+f"(c[3])
                 : "r"(a0), "r"(a1), "r"(a2), "r"(a3), "r"(b0), "r"(b1));
}
__device__ __forceinline__ u32 packbf(float x, float y) {
    __nv_bfloat16 bx = __float2bfloat16(x), by = __float2bfloat16(y);
    return (u32)__bfloat16_as_ushort(bx) | ((u32)__bfloat16_as_ushort(by) << 16);
}

// ---------------- scratch (device globals; BSS zero-init; padding never written) ----------
__device__ float g_xin[B_ * KIN_PAD];
__device__ float g_scale1[DENSE_N];
__device__ float g_shift1[DENSE_N];
__device__ float g_sc1[NC_ * 256], g_sh1[NC_ * 256];
__device__ float g_sc2[NC_ * 128], g_sh2[NC_ * 128];
__device__ __nv_bfloat16 g_x0h[B_ * 11 * 11 * 256], g_x0l[B_ * 11 * 11 * 256];
__device__ __nv_bfloat16 g_h1h[B_ * 9 * 9 * 256],   g_h1l[B_ * 9 * 9 * 256];
__device__ float g_h2[B_ * 16 * 16 * 128];
__device__ __nv_bfloat16 g_W1h[NC_ * 256 * 6400], g_W1l[NC_ * 256 * 6400];
__device__ __nv_bfloat16 g_W2h[NC_ * 4 * 128 * 2304], g_W2l[NC_ * 4 * 128 * 2304];
__device__ float g_tb1[NC_ * 25 * 256];      // per-(class,tap,co) embedding bias
__device__ float g_pb1[NC_ * 49 * 256];      // per-(class,pos,co) summed bias
__device__ int g_order[B_];
__device__ int g_cstart[NC_ + 1];
__device__ int g_aoff1[6400];
__device__ int g_aoff2[4 * 2304];
__device__ int g_wrow2[4 * 2304];

// ---------------- per-class bucketing -----------------------------------------------------
__global__ void k_classify(const int* __restrict__ labels) {
    __shared__ int slab[B_];
    __shared__ int spre[NC_ + 1];
    int t = threadIdx.x;
    slab[t] = labels[t];
    __syncthreads();
    int c = slab[t];
    int rank = 0;
    for (int j = 0; j < t; j++) rank += (slab[j] == c) ? 1 : 0;
    if (t == 0) {
        int cnt[NC_];
        for (int i = 0; i < NC_; i++) cnt[i] = 0;
        for (int j = 0; j < B_; j++) cnt[slab[j]]++;
        int acc = 0;
        for (int i = 0; i < NC_; i++) { spre[i] = acc; g_cstart[i] = acc; acc += cnt[i]; }
        spre[NC_] = acc; g_cstart[NC_] = acc;
    }
    __syncthreads();
    g_order[spre[c] + rank] = t;
}

// ---------------- dense input concat ----------------------------------------------------
__global__ void k_xin(const float* __restrict__ noise, const float* __restrict__ emb,
                      const int* __restrict__ labels) {
    int idx = blockIdx.x * blockDim.x + threadIdx.x;
    if (idx >= B_ * KIN) return;
    int b = idx / KIN, k = idx - b * KIN;
    float v = (k < NOISE_) ? noise[b * NOISE_ + k]
                           : emb[labels[b] * EMB_ + (k - NOISE_)];
    g_xin[b * KIN_PAD + k] = v;
}

// ---------------- BN folds ----------------------------------------------------------------
__global__ void k_bnscale1(const float* __restrict__ g, const float* __restrict__ bb,
                           const float* __restrict__ m, const float* __restrict__ v) {
    int i = blockIdx.x * blockDim.x + threadIdx.x;
    if (i >= DENSE_N) return;
    float s = g[i] * rsqrtf(v[i] + EPSBN);
    g_scale1[i] = s;
    g_shift1[i] = bb[i] - m[i] * s;
}

__global__ void k_bnbranch(const float* __restrict__ G1, const float* __restrict__ Bb1,
                           const float* __restrict__ M1, const float* __restrict__ V1,
                           const float* __restrict__ G2, const float* __restrict__ Bb2,
                           const float* __restrict__ M2, const float* __restrict__ V2) {
    int i = blockIdx.x * blockDim.x + threadIdx.x;
    if (i < NC_ * 256) {
        float s = G1[i] * rsqrtf(V1[i] + EPSBN);
        g_sc1[i] = s; g_sh1[i] = Bb1[i] - M1[i] * s;
    } else if (i < NC_ * 256 + NC_ * 128) {
        int j = i - NC_ * 256;
        float s = G2[j] * rsqrtf(V2[j] + EPSBN);
        g_sc2[j] = s; g_sh2[j] = Bb2[j] - M2[j] * s;
    }
}

// ---------------- gather/weight-row tables ------------------------------------------------
__global__ void k_tables() {
    int i = blockIdx.x * blockDim.x + threadIdx.x;
    if (i < 6400) {
        int tap = i >> 8, ci = i & 255;
        int kh = tap / 5, kw = tap - kh * 5;
        g_aoff1[i] = (kh * 11 + kw) * 256 + ci;
    } else if (i < 6400 + 4 * 2304) {
        int i2 = i - 6400;
        int par = i2 / 2304, q = i2 - par * 2304;
        int a = par >> 1, pb = par & 1;
        int nh = a ? 3 : 2, nw = pb ? 3 : 2;
        int Kp = nh * nw * 256;
        if (q < Kp) {
            int th = q / (nw * 256);
            int r = q - th * (nw * 256);
            int tw = r / 256, ci = r & 255;
            int kh = 2 * th + (a ? 0 : 1);
            int kw = 2 * tw + (pb ? 0 : 1);
            g_aoff2[par * 2304 + q] = (th * 9 + tw) * 256 + ci;
            g_wrow2[par * 2304 + q] = (kh * 5 + kw) * 256 + ci;
        }
    }
}

// ---------------- embedding bias precompute ----------------------------------------------
// TB[c][tap][co] = sum_e emb[c][e] * K1[c][tap][256+e][co]
__global__ void k_bias1(const float* __restrict__ emb, const float* __restrict__ K1) {
    int co = threadIdx.x;
    int tap = blockIdx.x, c = blockIdx.y;
    const float* kp = K1 + ((size_t)(c * 25 + tap) * 306 + 256) * 256 + co;
    const float* ep = emb + c * EMB_;
    float s = 0.f;
#pragma unroll 10
    for (int e = 0; e < EMB_; e++) s += ep[e] * kp[(size_t)e * 256];
    g_tb1[(c * 25 + tap) * 256 + co] = s;
}
// PB[c][pos][co] = sum over valid taps of TB
__global__ void k_bias2() {
    int co = threadIdx.x;
    int pos = blockIdx.x, c = blockIdx.y;
    int h = pos / 7, w = pos - h * 7;
    int khl = (2 - h) > 0 ? (2 - h) : 0, khh = (8 - h) < 4 ? (8 - h) : 4;
    int kwl = (2 - w) > 0 ? (2 - w) : 0, kwh = (8 - w) < 4 ? (8 - w) : 4;
    float s = 0.f;
    for (int kh = khl; kh <= khh; kh++)
        for (int kw = kwl; kw <= kwh; kw++)
            s += g_tb1[(c * 25 + kh * 5 + kw) * 256 + co];
    g_pb1[(c * 49 + pos) * 256 + co] = s;
}

// ---------------- weight transpose + hi/lo split -----------------------------------------
// K1 feature part only: k = tap*256+ci (ci<256) -> W1 [c][co][6400]
__global__ void k_wsplit1(const float* __restrict__ K1) {
    __shared__ float s[64][33];
    int cot = blockIdx.x, kt = blockIdx.y, c = blockIdx.z;
    int tid = threadIdx.x;
#pragma unroll
    for (int l = 0; l < 8; l++) {
        int idx = tid + l * 256;
        int kk = idx >> 5, coI = idx & 31;
        int k = kt * 64 + kk;
        int tap = k >> 8, ci = k & 255;
        s[kk][coI] = K1[((size_t)(c * 25 + tap) * 306 + ci) * 256 + cot * 32 + coI];
    }
    __syncthreads();
#pragma unroll
    for (int l = 0; l < 8; l++) {
        int idx = tid + l * 256;
        int co2 = idx >> 6, k2 = idx & 63;
        float v = s[k2][co2];
        __nv_bfloat16 hi = __float2bfloat16(v);
        __nv_bfloat16 lo = __float2bfloat16(v - __bfloat162float(hi));
        size_t o = ((size_t)(c * 256 + cot * 32 + co2)) * 6400 + kt * 64 + k2;
        g_W1h[o] = hi; g_W1l[o] = lo;
    }
}

__global__ void k_wsplit2(const float* __restrict__ K2) {
    __shared__ float s[64][33];
    int par = blockIdx.x >> 2, cot = blockIdx.x & 3;
    int kt = blockIdx.y, c = blockIdx.z;
    int Kp = (2 + (par >> 1)) * (2 + (par & 1)) * 256;
    int tid = threadIdx.x;
#pragma unroll
    for (int l = 0; l < 8; l++) {
        int idx = tid + l * 256;
        int kk = idx >> 5, coI = idx & 31;
        int k = kt * 64 + kk;
        float v = 0.f;
        if (k < Kp) {
            int row = g_wrow2[par * 2304 + k];
            v = K2[((size_t)c * 6400 + row) * 128 + cot * 32 + coI];
        }
        s[kk][coI] = v;
    }
    __syncthreads();
#pragma unroll
    for (int l = 0; l < 8; l++) {
        int idx = tid + l * 256;
        int co2 = idx >> 6, k2 = idx & 63;
        float v = s[k2][co2];
        __nv_bfloat16 hi = __float2bfloat16(v);
        __nv_bfloat16 lo = __float2bfloat16(v - __bfloat162float(hi));
        size_t o = ((size_t)((c * 4 + par) * 128 + cot * 32 + co2)) * 2304 + kt * 64 + k2;
        g_W2h[o] = hi; g_W2l[o] = lo;
    }
}

// ---------------- dense GEMM + bn + lrelu -> x0 hi/lo bf16 (256 chan) --------------------
__global__ __launch_bounds__(256) void k_dense(const float* __restrict__ Wd) {
    __shared__ float As[2][TK][TM + 4];
    __shared__ float Bs[2][TK][TN];
    int tid = threadIdx.x, tx = tid & 15, ty = tid >> 4;
    int row0 = blockIdx.y * TM;
    int col0 = blockIdx.x * TN;
    int ar = tid >> 2, ak = (tid & 3) * 4;
    int bkk = tid >> 4, bn = (tid & 15) * 4;
    const float* arow = g_xin + (size_t)(row0 + ar) * KIN_PAD;

    u64 acc[4][2];
#pragma unroll
    for (int i = 0; i < 4; i++) { acc[i][0] = 0ull; acc[i][1] = 0ull; }

    const int nT = KIN_PAD / TK;
    float a_reg[4]; float4 b_reg;
    {
#pragma unroll
        for (int i = 0; i < 4; i++) a_reg[i] = arow[ak + i];
        int k = bkk;
        b_reg = (k < KIN) ? *(const float4*)(Wd + (size_t)k * DENSE_N + col0 + bn)
                          : make_float4(0.f, 0.f, 0.f, 0.f);
    }
    int buf = 0;
    for (int t = 0; t < nT; t++) {
#pragma unroll
        for (int i = 0; i < 4; i++) As[buf][ak + i][ar] = a_reg[i];
        *(float4*)&Bs[buf][bkk][bn] = b_reg;
        __syncthreads();
        if (t + 1 < nT) {
            int k0 = (t + 1) * TK;
#pragma unroll
            for (int i = 0; i < 4; i++) a_reg[i] = arow[k0 + ak + i];
            int k = k0 + bkk;
            b_reg = (k < KIN) ? *(const float4*)(Wd + (size_t)k * DENSE_N + col0 + bn)
                              : make_float4(0.f, 0.f, 0.f, 0.f);
        }
#pragma unroll
        for (int kk = 0; kk < TK; kk++) {
            float4 av = *(const float4*)&As[buf][kk][ty * 4];
            u64 b0 = *(const u64*)&Bs[buf][kk][tx * 4];
            u64 b1 = *(const u64*)&Bs[buf][kk][tx * 4 + 2];
            float aa[4] = {av.x, av.y, av.z, av.w};
#pragma unroll
            for (int i = 0; i < 4; i++) {
                u64 ad = pk2(aa[i], aa[i]);
                acc[i][0] = ffma2(ad, b0, acc[i][0]);
                acc[i][1] = ffma2(ad, b1, acc[i][1]);
            }
        }
        __syncthreads();
        buf ^= 1;
    }
#pragma unroll
    for (int i = 0; i < 4; i++) {
        int b = row0 + ty * 4 + i;
        float y4[4];
        upk2(acc[i][0], y4[0], y4[1]);
        upk2(acc[i][1], y4[2], y4[3]);
        int jc0 = col0 + tx * 4;
#pragma unroll
        for (int j = 0; j < 4; j++) {
            int jc = jc0 + j;
            float y = y4[j] * g_scale1[jc] + g_shift1[jc];
            y4[j] = (y >= 0.f) ? y : ALPHA * y;
        }
        int h = jc0 / 1792;
        int w = (jc0 >> 8) % 7;
        int ch = jc0 & 255;
        size_t xb = ((size_t)(b * 11 + h + 2) * 11 + (w + 2)) * 256 + ch;
        float hi0 = __bfloat162float(__float2bfloat16(y4[0]));
        float hi1 = __bfloat162float(__float2bfloat16(y4[1]));
        float hi2 = __bfloat162float(__float2bfloat16(y4[2]));
        float hi3 = __bfloat162float(__float2bfloat16(y4[3]));
        *(u32*)&g_x0h[xb]     = packbf(y4[0], y4[1]);
        *(u32*)&g_x0h[xb + 2] = packbf(y4[2], y4[3]);
        *(u32*)&g_x0l[xb]     = packbf(y4[0] - hi0, y4[1] - hi1);
        *(u32*)&g_x0l[xb + 2] = packbf(y4[2] - hi2, y4[3] - hi3);
    }
}

// ---------------- fused 3-combo bf16 mma gather-GEMM (R8-verified access patterns) -------
// Single K sweep; per 32-k slab the Ah/Al/Bh/Bl smem planes are filled once, then
// combos Ah*Bh + Al*Bh + Ah*Bl issued (fp32 accum). Single buffer; A prefetched in
// regs across the tail sync (safe: planes rewritten only after both syncs).
__global__ __launch_bounds__(256, 2) void k_mma(int mode) {
    __shared__ __nv_bfloat16 P[4 * PLANE];   // 0=Ah 1=Al 2=Bh 3=Bl (40960 B)
    __shared__ int sAidx[128];

    int c = blockIdx.z;
    int s0 = g_cstart[c];
    int rows = (g_cstart[c + 1] - s0) * 49;
    int row0 = blockIdx.y * 128;
    if (row0 >= rows) return;

    const __nv_bfloat16 *Ahp, *Alp, *Bhp, *Blp;
    const int* aoff;
    int K, N, Wstride, col0;
    int a_bs, a_pw;
    const float *sc, *sh;
    const float* pbp = 0;
    int o_bs, o_rs, o_h0, o_hs, o_w0, o_ws;
    if (mode == 0) {
        Ahp = g_x0h; Alp = g_x0l;
        col0 = blockIdx.x * 128;
        Bhp = g_W1h + (size_t)(c * 256 + col0) * 6400;
        Blp = g_W1l + (size_t)(c * 256 + col0) * 6400;
        Wstride = 6400; aoff = g_aoff1; K = 6400; N = 256;
        a_bs = 121 * 256; a_pw = 11;
        sc = g_sc1 + c * 256; sh = g_sh1 + c * 256;
        pbp = g_pb1 + (size_t)c * 49 * 256;
        o_bs = 81 * 256; o_rs = 9 * 256; o_h0 = 1; o_hs = 1; o_w0 = 1; o_ws = 1;
    } else {
        int par = blockIdx.x;
        Ahp = g_h1h; Alp = g_h1l;
        col0 = 0;
        Bhp = g_W2h + (size_t)((c * 4 + par) * 128) * 2304;
        Blp = g_W2l + (size_t)((c * 4 + par) * 128) * 2304;
        Wstride = 2304; aoff = g_aoff2 + par * 2304;
        K = (2 + (par >> 1)) * (2 + (par & 1)) * 256; N = 128;
        a_bs = 81 * 256; a_pw = 9;
        sc = g_sc2 + c * 128; sh = g_sh2 + c * 128;
        o_bs = 256 * 128; o_rs = 16 * 128;
        o_h0 = (par >> 1) + 1; o_hs = 2; o_w0 = (par & 1) + 1; o_ws = 2;
    }

    __nv_bfloat16* Ahs = P;
    __nv_bfloat16* Als = P + PLANE;
    __nv_bfloat16* Bhs = P + 2 * PLANE;
    __nv_bfloat16* Bls = P + 3 * PLANE;

    int tid = threadIdx.x;
    if (tid < 128) {
        int r = row0 + tid;
        int ai = -1;
        if (r < rows) {
            int sl = r / 49, pos = r - sl * 49;
            int b = g_order[s0 + sl];
            int h = pos / 7, w = pos - h * 7;
            ai = b * a_bs + (h * a_pw + w) * 256;
        }
        sAidx[tid] = ai;
    }
    __syncthreads();

    // fill assignments (R8 pattern: lanes sweep k within a row)
    int kq = (tid & 15) * 2;        // A: k pair within 32-slab
    int rA = tid >> 4;              // A: rows rA + j*16
    int bq = (tid & 3) * 8;         // B: 8-elem (16B) quarter of 32-slab
    int rB = tid >> 2;              // B: rows rB + j*64
    int aidxA[8];
#pragma unroll
    for (int j = 0; j < 8; j++) aidxA[j] = sAidx[rA + j * 16];

    // warp / fragment ids
    int wid = tid >> 5, lane = tid & 31;
    int g = lane >> 2, tg = lane & 3;
    int wm = (wid >> 2) * 64, wn = (wid & 3) * 32;

    float acc[4][4][4];
#pragma unroll
    for (int mi = 0; mi < 4; mi++)
#pragma unroll
        for (int ni = 0; ni < 4; ni++)
#pragma unroll
            for (int q = 0; q < 4; q++) acc[mi][ni][q] = 0.f;

    int nT = K / 32;
    u32 pah[8], pal[8];

    // prefetch slab 0 (A only; B loaded at store point)
    {
        int ao = aoff[kq];
#pragma unroll
        for (int j = 0; j < 8; j++) {
            pah[j] = (aidxA[j] >= 0) ? *(const u32*)(Ahp + aidxA[j] + ao) : 0u;
            pal[j] = (aidxA[j] >= 0) ? *(const u32*)(Alp + aidxA[j] + ao) : 0u;
        }
    }

    for (int t = 0; t < nT; t++) {
        int kb = t * 32;
        // store A (from prefetch regs)
#pragma unroll
        for (int j = 0; j < 8; j++) {
            int off = (rA + j * 16) * PIT + kq;
            *(u32*)&Ahs[off] = pah[j];
            *(u32*)&Als[off] = pal[j];
        }
        // load + store B (short-lived regs)
#pragma unroll
        for (int j = 0; j < 2; j++) {
            int row = rB + j * 64;
            size_t se = (size_t)row * Wstride + kb + bq;
            uint4 vh = *(const uint4*)(Bhp + se);
            uint4 vl = *(const uint4*)(Blp + se);
            *(uint4*)&Bhs[row * PIT + bq] = vh;
            *(uint4*)&Bls[row * PIT + bq] = vl;
        }
        __syncthreads();
        // prefetch A for next slab (overlaps compute)
        if (t + 1 < nT) {
            int ao = aoff[kb + 32 + kq];
#pragma unroll
            for (int j = 0; j < 8; j++) {
                pah[j] = (aidxA[j] >= 0) ? *(const u32*)(Ahp + aidxA[j] + ao) : 0u;
                pal[j] = (aidxA[j] >= 0) ? *(const u32*)(Alp + aidxA[j] + ao) : 0u;
            }
        }
#pragma unroll
        for (int ks = 0; ks < 2; ks++) {
            int kb16 = ks * 16;
            u32 bf[4][2];
            // phase 1: Bh combos (Ah*Bh, Al*Bh)
#pragma unroll
            for (int ni = 0; ni < 4; ni++) {
                const __nv_bfloat16* bp = &Bhs[(wn + ni * 8 + g) * PIT + kb16 + tg * 2];
                bf[ni][0] = *(const u32*)bp;
                bf[ni][1] = *(const u32*)(bp + 8);
            }
#pragma unroll
            for (int mi = 0; mi < 4; mi++) {
                const __nv_bfloat16* ap = &Ahs[(wm + mi * 16 + g) * PIT + kb16 + tg * 2];
                u32 a0 = *(const u32*)ap;
                u32 a1 = *(const u32*)(ap + 8 * PIT);
                u32 a2 = *(const u32*)(ap + 8);
                u32 a3 = *(const u32*)(ap + 8 * PIT + 8);
                const __nv_bfloat16* lp = &Als[(wm + mi * 16 + g) * PIT + kb16 + tg * 2];
                u32 l0 = *(const u32*)lp;
                u32 l1 = *(const u32*)(lp + 8 * PIT);
                u32 l2 = *(const u32*)(lp + 8);
                u32 l3 = *(const u32*)(lp + 8 * PIT + 8);
#pragma unroll
                for (int ni = 0; ni < 4; ni++) {
                    mma16816(acc[mi][ni], a0, a1, a2, a3, bf[ni][0], bf[ni][1]);
                    mma16816(acc[mi][ni], l0, l1, l2, l3, bf[ni][0], bf[ni][1]);
                }
            }
            // phase 2: Bl combo (Ah*Bl)
#pragma unroll
            for (int ni = 0; ni < 4; ni++) {
                const __nv_bfloat16* bp = &Bls[(wn + ni * 8 + g) * PIT + kb16 + tg * 2];
                bf[ni][0] = *(const u32*)bp;
                bf[ni][1] = *(const u32*)(bp + 8);
            }
#pragma unroll
            for (int mi = 0; mi < 4; mi++) {
                const __nv_bfloat16* ap = &Ahs[(wm + mi * 16 + g) * PIT + kb16 + tg * 2];
                u32 a0 = *(const u32*)ap;
                u32 a1 = *(const u32*)(ap + 8 * PIT);
                u32 a2 = *(const u32*)(ap + 8);
                u32 a3 = *(const u32*)(ap + 8 * PIT + 8);
#pragma unroll
                for (int ni = 0; ni < 4; ni++)
                    mma16816(acc[mi][ni], a0, a1, a2, a3, bf[ni][0], bf[ni][1]);
            }
        }
        __syncthreads();
    }

    // epilogue: (+PB for mode0) bn + lrelu; mode0 -> h1 hi/lo bf16, mode1 -> h2 fp32
#pragma unroll
    for (int mi = 0; mi < 4; mi++) {
#pragma unroll
        for (int hh = 0; hh < 2; hh++) {
            int lr = wm + mi * 16 + g + hh * 8;
            int r = row0 + lr;
            if (r >= rows) continue;
            int sl = r / 49, pos = r - sl * 49;
            int b = g_order[s0 + sl];
            int h = pos / 7, w = pos - h * 7;
            size_t ob = (size_t)b * o_bs + (size_t)(o_h0 + h * o_hs) * o_rs
                      + (size_t)(o_w0 + w * o_ws) * (size_t)N;
            const float* pbrow = pbp ? (pbp + pos * 256) : 0;
#pragma unroll
            for (int ni = 0; ni < 4; ni++) {
                int co = wn + ni * 8 + tg * 2;
                int gco = col0 + co;
                float v0 = acc[mi][ni][hh * 2 + 0];
                float v1 = acc[mi][ni][hh * 2 + 1];
                if (pbrow) { v0 += pbrow[gco]; v1 += pbrow[gco + 1]; }
                v0 = v0 * sc[gco] + sh[gco];
                v1 = v1 * sc[gco + 1] + sh[gco + 1];
                v0 = (v0 >= 0.f) ? v0 : ALPHA * v0;
                v1 = (v1 >= 0.f) ? v1 : ALPHA * v1;
                if (mode == 0) {
                    float h0 = __bfloat162float(__float2bfloat16(v0));
                    float h1 = __bfloat162float(__float2bfloat16(v1));
                    *(u32*)&g_h1h[ob + gco] = packbf(v0, v1);
                    *(u32*)&g_h1l[ob + gco] = packbf(v0 - h0, v1 - h1);
                } else {
                    *(float2*)&g_h2[ob + gco] = make_float2(v0, v1);
                }
            }
        }
    }
}

// ---------------- ConvT3 (N=1) + tanh ----------------------------------------------------
__global__ __launch_bounds__(256) void k_convt3(const float* __restrict__ K3,
                                                const int* __restrict__ labels,
                                                float* __restrict__ out) {
    int b = blockIdx.x;
    int c = labels[b];
    __shared__ float Ks[5 * 5 * 128];
    for (int i = threadIdx.x; i < 5 * 5 * 128; i += blockDim.x)
        Ks[i] = K3[c * (5 * 5 * 128) + i];
    __syncthreads();
    const float* hb = g_h2 + (size_t)b * 16 * 16 * 128;
    for (int p = threadIdx.x; p < 784; p += blockDim.x) {
        int oh = p / 28, ow = p - oh * 28;
        int i = oh >> 1, a = oh & 1, j = ow >> 1, pb = ow & 1;
        int nh = a ? 3 : 2, nw = pb ? 3 : 2;
        float acc = 0.f;
        for (int th = 0; th < nh; th++) {
            int kh = 2 * th + (a ? 0 : 1);
            int ph = i + th;
            for (int tw = 0; tw < nw; tw++) {
                int kw = 2 * tw + (pb ? 0 : 1);
                int pw = j + tw;
                const float* xp = hb + (size_t)(ph * 16 + pw) * 128;
                const float* wp = Ks + (kh * 5 + kw) * 128;
#pragma unroll
                for (int ci = 0; ci < 128; ci += 4) {
                    float4 xv = *(const float4*)(xp + ci);
                    float4 wv = *(const float4*)(wp + ci);
                    acc += xv.x * wv.x + xv.y * wv.y + xv.z * wv.z + xv.w * wv.w;
                }
            }
        }
        out[(size_t)b * 784 + p] = tanhf(acc);
    }
}

// ---------------- launch ----------------------------------------------------------------
extern "C" void kernel_launch(void* const* d_in, const int* in_sizes, int n_in,
                              void* d_out, int out_size) {
    const float* noise = (const float*)d_in[0];
    const int*   labels = (const int*)d_in[1];
    const float* emb  = (const float*)d_in[2];
    const float* Wd   = (const float*)d_in[3];
    const float* bn1_g = (const float*)d_in[4];
    const float* bn1_b = (const float*)d_in[5];
    const float* bn1_m = (const float*)d_in[6];
    const float* bn1_v = (const float*)d_in[7];
    const float* K1 = (const float*)d_in[8];
    const float* G1 = (const float*)d_in[9];
    const float* B1 = (const float*)d_in[10];
    const float* M1 = (const float*)d_in[11];
    const float* V1 = (const float*)d_in[12];
    const float* K2 = (const float*)d_in[13];
    const float* G2 = (const float*)d_in[14];
    const float* B2 = (const float*)d_in[15];
    const float* M2 = (const float*)d_in[16];
    const float* V2 = (const float*)d_in[17];
    const float* K3 = (const float*)d_in[18];
    float* out = (float*)d_out;

    k_classify<<<1, B_>>>(labels);
    k_xin<<<(B_ * KIN + 255) / 256, 256>>>(noise, emb, labels);
    k_bnscale1<<<(DENSE_N + 255) / 256, 256>>>(bn1_g, bn1_b, bn1_m, bn1_v);
    k_bnbranch<<<(NC_ * 256 + NC_ * 128 + 255) / 256, 256>>>(G1, B1, M1, V1, G2, B2, M2, V2);
    k_tables<<<(6400 + 4 * 2304 + 255) / 256, 256>>>();

    k_wsplit1<<<dim3(8, 100, NC_), 256>>>(K1);
    k_wsplit2<<<dim3(16, 36, NC_), 256>>>(K2);
    k_bias1<<<dim3(25, NC_), 256>>>(emb, K1);
    k_bias2<<<dim3(49, NC_), 256>>>();

    k_dense<<<dim3(DENSE_N / TN, B_ / TM), 256>>>(Wd);

    // ConvT1: 2 col tiles x row tiles x classes (empty tiles exit)
    k_mma<<<dim3(2, (B_ * 49 + 127) / 128, NC_), 256>>>(0);
    // ConvT2: 4 parities x row tiles x classes
    k_mma<<<dim3(4, (B_ * 49 + 127) / 128, NC_), 256>>>(1);

    k_convt3<<<B_, 256>>>(K3, labels, out);
    (void)in_sizes; (void)n_in; (void)out_size;
}

// round 14
// speedup vs baseline: 2.5877x; 1.1849x over previous
#include <cuda_runtime.h>
#include <cuda_bf16.h>

#define ALPHA 0.3f
#define EPSBN 1e-3f

#define B_ 512
#define NOISE_ 100
#define NC_ 10
#define EMB_ 50
#define DENSE_N 12544   /* 7*7*256 */
#define KIN 150
#define KIN_PAD 160

/* dense GEMM tile */
#define TM 64
#define TN 64
#define TK 16

/* mma smem pitch (bf16 elems per 32-k slab row) */
#define PIT 40
#define PLANE_A (64 * PIT)
#define PLANE_BN (128 * PIT)

typedef unsigned int u32;
typedef unsigned long long u64;

__device__ __forceinline__ u64 pk2(float lo, float hi) {
    u64 r; asm("mov.b64 %0, {%1, %2};" : "=l"(r) : "f"(lo), "f"(hi)); return r;
}
__device__ __forceinline__ u64 ffma2(u64 a, u64 b, u64 c) {
    u64 d; asm("fma.rn.f32x2 %0, %1, %2, %3;" : "=l"(d) : "l"(a), "l"(b), "l"(c)); return d;
}
__device__ __forceinline__ void upk2(u64 v, float& lo, float& hi) {
    asm("mov.b64 {%0, %1}, %2;" : "=f"(lo), "=f"(hi) : "l"(v));
}
__device__ __forceinline__ void mma16816(float* c, u32 a0, u32 a1, u32 a2, u32 a3,
                                         u32 b0, u32 b1) {
    asm volatile("mma.sync.aligned.m16n8k16.row.col.f32.bf16.bf16.f32 "
                 "{%0,%1,%2,%3}, {%4,%5,%6,%7}, {%8,%9}, {%0,%1,%2,%3};"
                 : "+f"(c[0]), "+f"(c[1]), "+f"(c[2]), "+f"(c[3])
                 : "r"(a0), "r"(a1), "r"(a2), "r"(a3), "r"(b0), "r"(b1));
}
__device__ __forceinline__ u32 packbf(float x, float y) {
    __nv_bfloat16 bx = __float2bfloat16(x), by = __float2bfloat16(y);
    return (u32)__bfloat16_as_ushort(bx) | ((u32)__bfloat16_as_ushort(by) << 16);
}

// ---------------- scratch (device globals; BSS zero-init; padding never written) ----------
__device__ float g_xin[B_ * KIN_PAD];
__device__ float g_scale1[DENSE_N];
__device__ float g_shift1[DENSE_N];
__device__ float g_sc1[NC_ * 256], g_sh1[NC_ * 256];
__device__ float g_sc2[NC_ * 128], g_sh2[NC_ * 128];
__device__ __nv_bfloat16 g_x0h[B_ * 11 * 11 * 256], g_x0l[B_ * 11 * 11 * 256];
__device__ __nv_bfloat16 g_h1h[B_ * 9 * 9 * 256],   g_h1l[B_ * 9 * 9 * 256];
__device__ float g_h2[B_ * 16 * 16 * 128];
__device__ __nv_bfloat16 g_W1h[NC_ * 256 * 6400], g_W1l[NC_ * 256 * 6400];
__device__ __nv_bfloat16 g_W2h[NC_ * 4 * 128 * 2304], g_W2l[NC_ * 4 * 128 * 2304];
__device__ float g_tb1[NC_ * 25 * 256];      // per-(class,tap,co) embedding bias
__device__ float g_pb1[NC_ * 49 * 256];      // per-(class,pos,co) summed bias
__device__ int g_order[B_];
__device__ int g_cstart[NC_ + 1];
__device__ int g_aoff1[6400];
__device__ int g_aoff2[4 * 2304];
__device__ int g_wrow2[4 * 2304];

// ---------------- per-class bucketing -----------------------------------------------------
__global__ void k_classify(const int* __restrict__ labels) {
    __shared__ int slab[B_];
    __shared__ int spre[NC_ + 1];
    int t = threadIdx.x;
    slab[t] = labels[t];
    __syncthreads();
    int c = slab[t];
    int rank = 0;
    for (int j = 0; j < t; j++) rank += (slab[j] == c) ? 1 : 0;
    if (t == 0) {
        int cnt[NC_];
        for (int i = 0; i < NC_; i++) cnt[i] = 0;
        for (int j = 0; j < B_; j++) cnt[slab[j]]++;
        int acc = 0;
        for (int i = 0; i < NC_; i++) { spre[i] = acc; g_cstart[i] = acc; acc += cnt[i]; }
        spre[NC_] = acc; g_cstart[NC_] = acc;
    }
    __syncthreads();
    g_order[spre[c] + rank] = t;
}

// ---------------- dense input concat ----------------------------------------------------
__global__ void k_xin(const float* __restrict__ noise, const float* __restrict__ emb,
                      const int* __restrict__ labels) {
    int idx = blockIdx.x * blockDim.x + threadIdx.x;
    if (idx >= B_ * KIN) return;
    int b = idx / KIN, k = idx - b * KIN;
    float v = (k < NOISE_) ? noise[b * NOISE_ + k]
                           : emb[labels[b] * EMB_ + (k - NOISE_)];
    g_xin[b * KIN_PAD + k] = v;
}

// ---------------- BN folds ----------------------------------------------------------------
__global__ void k_bnscale1(const float* __restrict__ g, const float* __restrict__ bb,
                           const float* __restrict__ m, const float* __restrict__ v) {
    int i = blockIdx.x * blockDim.x + threadIdx.x;
    if (i >= DENSE_N) return;
    float s = g[i] * rsqrtf(v[i] + EPSBN);
    g_scale1[i] = s;
    g_shift1[i] = bb[i] - m[i] * s;
}

__global__ void k_bnbranch(const float* __restrict__ G1, const float* __restrict__ Bb1,
                           const float* __restrict__ M1, const float* __restrict__ V1,
                           const float* __restrict__ G2, const float* __restrict__ Bb2,
                           const float* __restrict__ M2, const float* __restrict__ V2) {
    int i = blockIdx.x * blockDim.x + threadIdx.x;
    if (i < NC_ * 256) {
        float s = G1[i] * rsqrtf(V1[i] + EPSBN);
        g_sc1[i] = s; g_sh1[i] = Bb1[i] - M1[i] * s;
    } else if (i < NC_ * 256 + NC_ * 128) {
        int j = i - NC_ * 256;
        float s = G2[j] * rsqrtf(V2[j] + EPSBN);
        g_sc2[j] = s; g_sh2[j] = Bb2[j] - M2[j] * s;
    }
}

// ---------------- gather/weight-row tables ------------------------------------------------
__global__ void k_tables() {
    int i = blockIdx.x * blockDim.x + threadIdx.x;
    if (i < 6400) {
        int tap = i >> 8, ci = i & 255;
        int kh = tap / 5, kw = tap - kh * 5;
        g_aoff1[i] = (kh * 11 + kw) * 256 + ci;
    } else if (i < 6400 + 4 * 2304) {
        int i2 = i - 6400;
        int par = i2 / 2304, q = i2 - par * 2304;
        int a = par >> 1, pb = par & 1;
        int nh = a ? 3 : 2, nw = pb ? 3 : 2;
        int Kp = nh * nw * 256;
        if (q < Kp) {
            int th = q / (nw * 256);
            int r = q - th * (nw * 256);
            int tw = r / 256, ci = r & 255;
            int kh = 2 * th + (a ? 0 : 1);
            int kw = 2 * tw + (pb ? 0 : 1);
            g_aoff2[par * 2304 + q] = (th * 9 + tw) * 256 + ci;
            g_wrow2[par * 2304 + q] = (kh * 5 + kw) * 256 + ci;
        }
    }
}

// ---------------- embedding bias precompute ----------------------------------------------
// TB[c][tap][co] = sum_e emb[c][e] * K1[c][tap][256+e][co]
__global__ void k_bias1(const float* __restrict__ emb, const float* __restrict__ K1) {
    int co = threadIdx.x;
    int tap = blockIdx.x, c = blockIdx.y;
    const float* kp = K1 + ((size_t)(c * 25 + tap) * 306 + 256) * 256 + co;
    const float* ep = emb + c * EMB_;
    float s = 0.f;
#pragma unroll 10
    for (int e = 0; e < EMB_; e++) s += ep[e] * kp[(size_t)e * 256];
    g_tb1[(c * 25 + tap) * 256 + co] = s;
}
// PB[c][pos][co] = sum over valid taps of TB
__global__ void k_bias2() {
    int co = threadIdx.x;
    int pos = blockIdx.x, c = blockIdx.y;
    int h = pos / 7, w = pos - h * 7;
    int khl = (2 - h) > 0 ? (2 - h) : 0, khh = (8 - h) < 4 ? (8 - h) : 4;
    int kwl = (2 - w) > 0 ? (2 - w) : 0, kwh = (8 - w) < 4 ? (8 - w) : 4;
    float s = 0.f;
    for (int kh = khl; kh <= khh; kh++)
        for (int kw = kwl; kw <= kwh; kw++)
            s += g_tb1[(c * 25 + kh * 5 + kw) * 256 + co];
    g_pb1[(c * 49 + pos) * 256 + co] = s;
}

// ---------------- weight transpose + hi/lo split -----------------------------------------
// K1 feature part only: k = tap*256+ci (ci<256) -> W1 [c][co][6400]
__global__ void k_wsplit1(const float* __restrict__ K1) {
    __shared__ float s[64][33];
    int cot = blockIdx.x, kt = blockIdx.y, c = blockIdx.z;
    int tid = threadIdx.x;
#pragma unroll
    for (int l = 0; l < 8; l++) {
        int idx = tid + l * 256;
        int kk = idx >> 5, coI = idx & 31;
        int k = kt * 64 + kk;
        int tap = k >> 8, ci = k & 255;
        s[kk][coI] = K1[((size_t)(c * 25 + tap) * 306 + ci) * 256 + cot * 32 + coI];
    }
    __syncthreads();
#pragma unroll
    for (int l = 0; l < 8; l++) {
        int idx = tid + l * 256;
        int co2 = idx >> 6, k2 = idx & 63;
        float v = s[k2][co2];
        __nv_bfloat16 hi = __float2bfloat16(v);
        __nv_bfloat16 lo = __float2bfloat16(v - __bfloat162float(hi));
        size_t o = ((size_t)(c * 256 + cot * 32 + co2)) * 6400 + kt * 64 + k2;
        g_W1h[o] = hi; g_W1l[o] = lo;
    }
}

__global__ void k_wsplit2(const float* __restrict__ K2) {
    __shared__ float s[64][33];
    int par = blockIdx.x >> 2, cot = blockIdx.x & 3;
    int kt = blockIdx.y, c = blockIdx.z;
    int Kp = (2 + (par >> 1)) * (2 + (par & 1)) * 256;
    int tid = threadIdx.x;
#pragma unroll
    for (int l = 0; l < 8; l++) {
        int idx = tid + l * 256;
        int kk = idx >> 5, coI = idx & 31;
        int k = kt * 64 + kk;
        float v = 0.f;
        if (k < Kp) {
            int row = g_wrow2[par * 2304 + k];
            v = K2[((size_t)c * 6400 + row) * 128 + cot * 32 + coI];
        }
        s[kk][coI] = v;
    }
    __syncthreads();
#pragma unroll
    for (int l = 0; l < 8; l++) {
        int idx = tid + l * 256;
        int co2 = idx >> 6, k2 = idx & 63;
        float v = s[k2][co2];
        __nv_bfloat16 hi = __float2bfloat16(v);
        __nv_bfloat16 lo = __float2bfloat16(v - __bfloat162float(hi));
        size_t o = ((size_t)((c * 4 + par) * 128 + cot * 32 + co2)) * 2304 + kt * 64 + k2;
        g_W2h[o] = hi; g_W2l[o] = lo;
    }
}

// ---------------- dense GEMM + bn + lrelu -> x0 hi/lo bf16 (256 chan) --------------------
__global__ __launch_bounds__(256) void k_dense(const float* __restrict__ Wd) {
    __shared__ float As[2][TK][TM + 4];
    __shared__ float Bs[2][TK][TN];
    int tid = threadIdx.x, tx = tid & 15, ty = tid >> 4;
    int row0 = blockIdx.y * TM;
    int col0 = blockIdx.x * TN;
    int ar = tid >> 2, ak = (tid & 3) * 4;
    int bkk = tid >> 4, bn = (tid & 15) * 4;
    const float* arow = g_xin + (size_t)(row0 + ar) * KIN_PAD;

    u64 acc[4][2];
#pragma unroll
    for (int i = 0; i < 4; i++) { acc[i][0] = 0ull; acc[i][1] = 0ull; }

    const int nT = KIN_PAD / TK;
    float a_reg[4]; float4 b_reg;
    {
#pragma unroll
        for (int i = 0; i < 4; i++) a_reg[i] = arow[ak + i];
        int k = bkk;
        b_reg = (k < KIN) ? *(const float4*)(Wd + (size_t)k * DENSE_N + col0 + bn)
                          : make_float4(0.f, 0.f, 0.f, 0.f);
    }
    int buf = 0;
    for (int t = 0; t < nT; t++) {
#pragma unroll
        for (int i = 0; i < 4; i++) As[buf][ak + i][ar] = a_reg[i];
        *(float4*)&Bs[buf][bkk][bn] = b_reg;
        __syncthreads();
        if (t + 1 < nT) {
            int k0 = (t + 1) * TK;
#pragma unroll
            for (int i = 0; i < 4; i++) a_reg[i] = arow[k0 + ak + i];
            int k = k0 + bkk;
            b_reg = (k < KIN) ? *(const float4*)(Wd + (size_t)k * DENSE_N + col0 + bn)
                              : make_float4(0.f, 0.f, 0.f, 0.f);
        }
#pragma unroll
        for (int kk = 0; kk < TK; kk++) {
            float4 av = *(const float4*)&As[buf][kk][ty * 4];
            u64 b0 = *(const u64*)&Bs[buf][kk][tx * 4];
            u64 b1 = *(const u64*)&Bs[buf][kk][tx * 4 + 2];
            float aa[4] = {av.x, av.y, av.z, av.w};
#pragma unroll
            for (int i = 0; i < 4; i++) {
                u64 ad = pk2(aa[i], aa[i]);
                acc[i][0] = ffma2(ad, b0, acc[i][0]);
                acc[i][1] = ffma2(ad, b1, acc[i][1]);
            }
        }
        __syncthreads();
        buf ^= 1;
    }
#pragma unroll
    for (int i = 0; i < 4; i++) {
        int b = row0 + ty * 4 + i;
        float y4[4];
        upk2(acc[i][0], y4[0], y4[1]);
        upk2(acc[i][1], y4[2], y4[3]);
        int jc0 = col0 + tx * 4;
#pragma unroll
        for (int j = 0; j < 4; j++) {
            int jc = jc0 + j;
            float y = y4[j] * g_scale1[jc] + g_shift1[jc];
            y4[j] = (y >= 0.f) ? y : ALPHA * y;
        }
        int h = jc0 / 1792;
        int w = (jc0 >> 8) % 7;
        int ch = jc0 & 255;
        size_t xb = ((size_t)(b * 11 + h + 2) * 11 + (w + 2)) * 256 + ch;
        float hi0 = __bfloat162float(__float2bfloat16(y4[0]));
        float hi1 = __bfloat162float(__float2bfloat16(y4[1]));
        float hi2 = __bfloat162float(__float2bfloat16(y4[2]));
        float hi3 = __bfloat162float(__float2bfloat16(y4[3]));
        *(u32*)&g_x0h[xb]     = packbf(y4[0], y4[1]);
        *(u32*)&g_x0h[xb + 2] = packbf(y4[2], y4[3]);
        *(u32*)&g_x0l[xb]     = packbf(y4[0] - hi0, y4[1] - hi1);
        *(u32*)&g_x0l[xb + 2] = packbf(y4[2] - hi2, y4[3] - hi3);
    }
}

// ---------------- fused 3-combo bf16 mma gather-GEMM, M=64 tiles, 3 CTAs/SM --------------
// Single K sweep; per 32-k slab the Ah/Al/Bh/Bl smem planes are filled once, then
// combos Ah*Bh + Al*Bh + Ah*Bl issued (fp32 accum). Single buffer; A prefetched in
// regs across the tail sync (safe: planes rewritten only after both syncs).
__global__ __launch_bounds__(256, 3) void k_mma(int mode) {
    __shared__ __nv_bfloat16 P[2 * PLANE_A + 2 * PLANE_BN];   // Ah,Al(64r) Bh,Bl(128r)
    __shared__ int sAidx[64];

    int c = blockIdx.z;
    int s0 = g_cstart[c];
    int rows = (g_cstart[c + 1] - s0) * 49;
    int row0 = blockIdx.y * 64;
    if (row0 >= rows) return;

    const __nv_bfloat16 *Ahp, *Alp, *Bhp, *Blp;
    const int* aoff;
    int K, N, Wstride, col0;
    int a_bs, a_pw;
    const float *sc, *sh;
    const float* pbp = 0;
    int o_bs, o_rs, o_h0, o_hs, o_w0, o_ws;
    if (mode == 0) {
        Ahp = g_x0h; Alp = g_x0l;
        col0 = blockIdx.x * 128;
        Bhp = g_W1h + (size_t)(c * 256 + col0) * 6400;
        Blp = g_W1l + (size_t)(c * 256 + col0) * 6400;
        Wstride = 6400; aoff = g_aoff1; K = 6400; N = 256;
        a_bs = 121 * 256; a_pw = 11;
        sc = g_sc1 + c * 256; sh = g_sh1 + c * 256;
        pbp = g_pb1 + (size_t)c * 49 * 256;
        o_bs = 81 * 256; o_rs = 9 * 256; o_h0 = 1; o_hs = 1; o_w0 = 1; o_ws = 1;
    } else {
        int par = blockIdx.x;
        Ahp = g_h1h; Alp = g_h1l;
        col0 = 0;
        Bhp = g_W2h + (size_t)((c * 4 + par) * 128) * 2304;
        Blp = g_W2l + (size_t)((c * 4 + par) * 128) * 2304;
        Wstride = 2304; aoff = g_aoff2 + par * 2304;
        K = (2 + (par >> 1)) * (2 + (par & 1)) * 256; N = 128;
        a_bs = 81 * 256; a_pw = 9;
        sc = g_sc2 + c * 128; sh = g_sh2 + c * 128;
        o_bs = 256 * 128; o_rs = 16 * 128;
        o_h0 = (par >> 1) + 1; o_hs = 2; o_w0 = (par & 1) + 1; o_ws = 2;
    }

    __nv_bfloat16* Ahs = P;
    __nv_bfloat16* Als = P + PLANE_A;
    __nv_bfloat16* Bhs = P + 2 * PLANE_A;
    __nv_bfloat16* Bls = P + 2 * PLANE_A + PLANE_BN;

    int tid = threadIdx.x;
    if (tid < 64) {
        int r = row0 + tid;
        int ai = -1;
        if (r < rows) {
            int sl = r / 49, pos = r - sl * 49;
            int b = g_order[s0 + sl];
            int h = pos / 7, w = pos - h * 7;
            ai = b * a_bs + (h * a_pw + w) * 256;
        }
        sAidx[tid] = ai;
    }
    __syncthreads();

    // fill assignments (lanes sweep k within a row)
    int kq = (tid & 15) * 2;        // A: k pair within 32-slab
    int rA = tid >> 4;              // A: rows rA + j*16, j<4
    int bq = (tid & 3) * 8;         // B: 8-elem (16B) quarter of 32-slab
    int rB = tid >> 2;              // B: rows rB + j*64, j<2
    int aidxA[4];
#pragma unroll
    for (int j = 0; j < 4; j++) aidxA[j] = sAidx[rA + j * 16];

    // warp / fragment ids: 8 warps as 2(m) x 4(n)
    int wid = tid >> 5, lane = tid & 31;
    int g = lane >> 2, tg = lane & 3;
    int wm = (wid >> 2) * 32, wn = (wid & 3) * 32;

    float acc[2][4][4];
#pragma unroll
    for (int mi = 0; mi < 2; mi++)
#pragma unroll
        for (int ni = 0; ni < 4; ni++)
#pragma unroll
            for (int q = 0; q < 4; q++) acc[mi][ni][q] = 0.f;

    int nT = K / 32;
    u32 pah[4], pal[4];

    // prefetch slab 0 (A only; B loaded at store point)
    {
        int ao = aoff[kq];
#pragma unroll
        for (int j = 0; j < 4; j++) {
            pah[j] = (aidxA[j] >= 0) ? *(const u32*)(Ahp + aidxA[j] + ao) : 0u;
            pal[j] = (aidxA[j] >= 0) ? *(const u32*)(Alp + aidxA[j] + ao) : 0u;
        }
    }

    for (int t = 0; t < nT; t++) {
        int kb = t * 32;
        // store A (from prefetch regs)
#pragma unroll
        for (int j = 0; j < 4; j++) {
            int off = (rA + j * 16) * PIT + kq;
            *(u32*)&Ahs[off] = pah[j];
            *(u32*)&Als[off] = pal[j];
        }
        // load + store B (short-lived regs)
#pragma unroll
        for (int j = 0; j < 2; j++) {
            int row = rB + j * 64;
            size_t se = (size_t)row * Wstride + kb + bq;
            uint4 vh = *(const uint4*)(Bhp + se);
            uint4 vl = *(const uint4*)(Blp + se);
            *(uint4*)&Bhs[row * PIT + bq] = vh;
            *(uint4*)&Bls[row * PIT + bq] = vl;
        }
        __syncthreads();
        // prefetch A for next slab (overlaps compute)
        if (t + 1 < nT) {
            int ao = aoff[kb + 32 + kq];
#pragma unroll
            for (int j = 0; j < 4; j++) {
                pah[j] = (aidxA[j] >= 0) ? *(const u32*)(Ahp + aidxA[j] + ao) : 0u;
                pal[j] = (aidxA[j] >= 0) ? *(const u32*)(Alp + aidxA[j] + ao) : 0u;
            }
        }
#pragma unroll
        for (int ks = 0; ks < 2; ks++) {
            int kb16 = ks * 16;
            u32 bf[4][2];
            // phase 1: Bh combos (Ah*Bh, Al*Bh)
#pragma unroll
            for (int ni = 0; ni < 4; ni++) {
                const __nv_bfloat16* bp = &Bhs[(wn + ni * 8 + g) * PIT + kb16 + tg * 2];
                bf[ni][0] = *(const u32*)bp;
                bf[ni][1] = *(const u32*)(bp + 8);
            }
#pragma unroll
            for (int mi = 0; mi < 2; mi++) {
                const __nv_bfloat16* ap = &Ahs[(wm + mi * 16 + g) * PIT + kb16 + tg * 2];
                u32 a0 = *(const u32*)ap;
                u32 a1 = *(const u32*)(ap + 8 * PIT);
                u32 a2 = *(const u32*)(ap + 8);
                u32 a3 = *(const u32*)(ap + 8 * PIT + 8);
                const __nv_bfloat16* lp = &Als[(wm + mi * 16 + g) * PIT + kb16 + tg * 2];
                u32 l0 = *(const u32*)lp;
                u32 l1 = *(const u32*)(lp + 8 * PIT);
                u32 l2 = *(const u32*)(lp + 8);
                u32 l3 = *(const u32*)(lp + 8 * PIT + 8);
#pragma unroll
                for (int ni = 0; ni < 4; ni++) {
                    mma16816(acc[mi][ni], a0, a1, a2, a3, bf[ni][0], bf[ni][1]);
                    mma16816(acc[mi][ni], l0, l1, l2, l3, bf[ni][0], bf[ni][1]);
                }
            }
            // phase 2: Bl combo (Ah*Bl)
#pragma unroll
            for (int ni = 0; ni < 4; ni++) {
                const __nv_bfloat16* bp = &Bls[(wn + ni * 8 + g) * PIT + kb16 + tg * 2];
                bf[ni][0] = *(const u32*)bp;
                bf[ni][1] = *(const u32*)(bp + 8);
            }
#pragma unroll
            for (int mi = 0; mi < 2; mi++) {
                const __nv_bfloat16* ap = &Ahs[(wm + mi * 16 + g) * PIT + kb16 + tg * 2];
                u32 a0 = *(const u32*)ap;
                u32 a1 = *(const u32*)(ap + 8 * PIT);
                u32 a2 = *(const u32*)(ap + 8);
                u32 a3 = *(const u32*)(ap + 8 * PIT + 8);
#pragma unroll
                for (int ni = 0; ni < 4; ni++)
                    mma16816(acc[mi][ni], a0, a1, a2, a3, bf[ni][0], bf[ni][1]);
            }
        }
        __syncthreads();
    }

    // epilogue: (+PB for mode0) bn + lrelu; mode0 -> h1 hi/lo bf16, mode1 -> h2 fp32
#pragma unroll
    for (int mi = 0; mi < 2; mi++) {
#pragma unroll
        for (int hh = 0; hh < 2; hh++) {
            int lr = wm + mi * 16 + g + hh * 8;
            int r = row0 + lr;
            if (r >= rows) continue;
            int sl = r / 49, pos = r - sl * 49;
            int b = g_order[s0 + sl];
            int h = pos / 7, w = pos - h * 7;
            size_t ob = (size_t)b * o_bs + (size_t)(o_h0 + h * o_hs) * o_rs
                      + (size_t)(o_w0 + w * o_ws) * (size_t)N;
            const float* pbrow = pbp ? (pbp + pos * 256) : 0;
#pragma unroll
            for (int ni = 0; ni < 4; ni++) {
                int co = wn + ni * 8 + tg * 2;
                int gco = col0 + co;
                float v0 = acc[mi][ni][hh * 2 + 0];
                float v1 = acc[mi][ni][hh * 2 + 1];
                if (pbrow) { v0 += pbrow[gco]; v1 += pbrow[gco + 1]; }
                v0 = v0 * sc[gco] + sh[gco];
                v1 = v1 * sc[gco + 1] + sh[gco + 1];
                v0 = (v0 >= 0.f) ? v0 : ALPHA * v0;
                v1 = (v1 >= 0.f) ? v1 : ALPHA * v1;
                if (mode == 0) {
                    float h0 = __bfloat162float(__float2bfloat16(v0));
                    float h1 = __bfloat162float(__float2bfloat16(v1));
                    *(u32*)&g_h1h[ob + gco] = packbf(v0, v1);
                    *(u32*)&g_h1l[ob + gco] = packbf(v0 - h0, v1 - h1);
                } else {
                    *(float2*)&g_h2[ob + gco] = make_float2(v0, v1);
                }
            }
        }
    }
}

// ---------------- ConvT3 (N=1) + tanh ----------------------------------------------------
__global__ __launch_bounds__(256) void k_convt3(const float* __restrict__ K3,
                                                const int* __restrict__ labels,
                                                float* __restrict__ out) {
    int b = blockIdx.x;
    int c = labels[b];
    __shared__ float Ks[5 * 5 * 128];
    for (int i = threadIdx.x; i < 5 * 5 * 128; i += blockDim.x)
        Ks[i] = K3[c * (5 * 5 * 128) + i];
    __syncthreads();
    const float* hb = g_h2 + (size_t)b * 16 * 16 * 128;
    for (int p = threadIdx.x; p < 784; p += blockDim.x) {
        int oh = p / 28, ow = p - oh * 28;
        int i = oh >> 1, a = oh & 1, j = ow >> 1, pb = ow & 1;
        int nh = a ? 3 : 2, nw = pb ? 3 : 2;
        float acc = 0.f;
        for (int th = 0; th < nh; th++) {
            int kh = 2 * th + (a ? 0 : 1);
            int ph = i + th;
            for (int tw = 0; tw < nw; tw++) {
                int kw = 2 * tw + (pb ? 0 : 1);
                int pw = j + tw;
                const float* xp = hb + (size_t)(ph * 16 + pw) * 128;
                const float* wp = Ks + (kh * 5 + kw) * 128;
#pragma unroll
                for (int ci = 0; ci < 128; ci += 4) {
                    float4 xv = *(const float4*)(xp + ci);
                    float4 wv = *(const float4*)(wp + ci);
                    acc += xv.x * wv.x + xv.y * wv.y + xv.z * wv.z + xv.w * wv.w;
                }
            }
        }
        out[(size_t)b * 784 + p] = tanhf(acc);
    }
}

// ---------------- launch ----------------------------------------------------------------
extern "C" void kernel_launch(void* const* d_in, const int* in_sizes, int n_in,
                              void* d_out, int out_size) {
    const float* noise = (const float*)d_in[0];
    const int*   labels = (const int*)d_in[1];
    const float* emb  = (const float*)d_in[2];
    const float* Wd   = (const float*)d_in[3];
    const float* bn1_g = (const float*)d_in[4];
    const float* bn1_b = (const float*)d_in[5];
    const float* bn1_m = (const float*)d_in[6];
    const float* bn1_v = (const float*)d_in[7];
    const float* K1 = (const float*)d_in[8];
    const float* G1 = (const float*)d_in[9];
    const float* B1 = (const float*)d_in[10];
    const float* M1 = (const float*)d_in[11];
    const float* V1 = (const float*)d_in[12];
    const float* K2 = (const float*)d_in[13];
    const float* G2 = (const float*)d_in[14];
    const float* B2 = (const float*)d_in[15];
    const float* M2 = (const float*)d_in[16];
    const float* V2 = (const float*)d_in[17];
    const float* K3 = (const float*)d_in[18];
    float* out = (float*)d_out;

    k_classify<<<1, B_>>>(labels);
    k_xin<<<(B_ * KIN + 255) / 256, 256>>>(noise, emb, labels);
    k_bnscale1<<<(DENSE_N + 255) / 256, 256>>>(bn1_g, bn1_b, bn1_m, bn1_v);
    k_bnbranch<<<(NC_ * 256 + NC_ * 128 + 255) / 256, 256>>>(G1, B1, M1, V1, G2, B2, M2, V2);
    k_tables<<<(6400 + 4 * 2304 + 255) / 256, 256>>>();

    k_wsplit1<<<dim3(8, 100, NC_), 256>>>(K1);
    k_wsplit2<<<dim3(16, 36, NC_), 256>>>(K2);
    k_bias1<<<dim3(25, NC_), 256>>>(emb, K1);
    k_bias2<<<dim3(49, NC_), 256>>>();

    k_dense<<<dim3(DENSE_N / TN, B_ / TM), 256>>>(Wd);

    // ConvT1: 2 col tiles x 64-row tiles x classes (empty tiles exit)
    k_mma<<<dim3(2, (B_ * 49 + 63) / 64, NC_), 256>>>(0);
    // ConvT2: 4 parities x 64-row tiles x classes
    k_mma<<<dim3(4, (B_ * 49 + 63) / 64, NC_), 256>>>(1);

    k_convt3<<<B_, 256>>>(K3, labels, out);
    (void)in_sizes; (void)n_in; (void)out_size;
}

// round 15
// speedup vs baseline: 2.8137x; 1.0873x over previous
#include <cuda_runtime.h>
#include <cuda_bf16.h>

#define ALPHA 0.3f
#define EPSBN 1e-3f

#define B_ 512
#define NOISE_ 100
#define NC_ 10
#define EMB_ 50
#define DENSE_N 12544   /* 7*7*256 */
#define KIN 150
#define KIN_PAD 160

/* dense GEMM tile */
#define TM 64
#define TN 64
#define TK 16

/* mma smem pitch (bf16 elems per 32-k slab row) */
#define PIT 40
#define PLANE_A (64 * PIT)
#define PLANE_BN (128 * PIT)

typedef unsigned int u32;
typedef unsigned long long u64;

__device__ __forceinline__ u64 pk2(float lo, float hi) {
    u64 r; asm("mov.b64 %0, {%1, %2};" : "=l"(r) : "f"(lo), "f"(hi)); return r;
}
__device__ __forceinline__ u64 ffma2(u64 a, u64 b, u64 c) {
    u64 d; asm("fma.rn.f32x2 %0, %1, %2, %3;" : "=l"(d) : "l"(a), "l"(b), "l"(c)); return d;
}
__device__ __forceinline__ void upk2(u64 v, float& lo, float& hi) {
    asm("mov.b64 {%0, %1}, %2;" : "=f"(lo), "=f"(hi) : "l"(v));
}
__device__ __forceinline__ void mma16816(float* c, u32 a0, u32 a1, u32 a2, u32 a3,
                                         u32 b0, u32 b1) {
    asm volatile("mma.sync.aligned.m16n8k16.row.col.f32.bf16.bf16.f32 "
                 "{%0,%1,%2,%3}, {%4,%5,%6,%7}, {%8,%9}, {%0,%1,%2,%3};"
                 : "+f"(c[0]), "+f"(c[1]), "+f"(c[2]), "+f"(c[3])
                 : "r"(a0), "r"(a1), "r"(a2), "r"(a3), "r"(b0), "r"(b1));
}
__device__ __forceinline__ u32 packbf(float x, float y) {
    __nv_bfloat16 bx = __float2bfloat16(x), by = __float2bfloat16(y);
    return (u32)__bfloat16_as_ushort(bx) | ((u32)__bfloat16_as_ushort(by) << 16);
}

// ---------------- scratch (device globals; BSS zero-init; padding never written) ----------
__device__ float g_xin[B_ * KIN_PAD];
__device__ float g_scale1[DENSE_N];
__device__ float g_shift1[DENSE_N];
__device__ float g_sc1[NC_ * 256], g_sh1[NC_ * 256];
__device__ float g_sc2[NC_ * 128], g_sh2[NC_ * 128];
__device__ __nv_bfloat16 g_x0h[B_ * 11 * 11 * 256], g_x0l[B_ * 11 * 11 * 256];
__device__ __nv_bfloat16 g_h1h[B_ * 9 * 9 * 256],   g_h1l[B_ * 9 * 9 * 256];
__device__ float g_h2[B_ * 16 * 16 * 128];
__device__ __nv_bfloat16 g_W1h[NC_ * 256 * 6400], g_W1l[NC_ * 256 * 6400];
__device__ __nv_bfloat16 g_W2h[NC_ * 4 * 128 * 2304], g_W2l[NC_ * 4 * 128 * 2304];
__device__ float g_tb1[NC_ * 25 * 256];      // per-(class,tap,co) embedding bias
__device__ float g_pb1[NC_ * 49 * 256];      // per-(class,pos,co) summed bias
__device__ int g_order[B_];
__device__ int g_cstart[NC_ + 1];
__device__ int g_wrow2[4 * 2304];

// ---------------- per-class bucketing -----------------------------------------------------
__global__ void k_classify(const int* __restrict__ labels) {
    __shared__ int slab[B_];
    __shared__ int spre[NC_ + 1];
    int t = threadIdx.x;
    slab[t] = labels[t];
    __syncthreads();
    int c = slab[t];
    int rank = 0;
    for (int j = 0; j < t; j++) rank += (slab[j] == c) ? 1 : 0;
    if (t == 0) {
        int cnt[NC_];
        for (int i = 0; i < NC_; i++) cnt[i] = 0;
        for (int j = 0; j < B_; j++) cnt[slab[j]]++;
        int acc = 0;
        for (int i = 0; i < NC_; i++) { spre[i] = acc; g_cstart[i] = acc; acc += cnt[i]; }
        spre[NC_] = acc; g_cstart[NC_] = acc;
    }
    __syncthreads();
    g_order[spre[c] + rank] = t;
}

// ---------------- dense input concat ----------------------------------------------------
__global__ void k_xin(const float* __restrict__ noise, const float* __restrict__ emb,
                      const int* __restrict__ labels) {
    int idx = blockIdx.x * blockDim.x + threadIdx.x;
    if (idx >= B_ * KIN) return;
    int b = idx / KIN, k = idx - b * KIN;
    float v = (k < NOISE_) ? noise[b * NOISE_ + k]
                           : emb[labels[b] * EMB_ + (k - NOISE_)];
    g_xin[b * KIN_PAD + k] = v;
}

// ---------------- BN folds ----------------------------------------------------------------
__global__ void k_bnscale1(const float* __restrict__ g, const float* __restrict__ bb,
                           const float* __restrict__ m, const float* __restrict__ v) {
    int i = blockIdx.x * blockDim.x + threadIdx.x;
    if (i >= DENSE_N) return;
    float s = g[i] * rsqrtf(v[i] + EPSBN);
    g_scale1[i] = s;
    g_shift1[i] = bb[i] - m[i] * s;
}

__global__ void k_bnbranch(const float* __restrict__ G1, const float* __restrict__ Bb1,
                           const float* __restrict__ M1, const float* __restrict__ V1,
                           const float* __restrict__ G2, const float* __restrict__ Bb2,
                           const float* __restrict__ M2, const float* __restrict__ V2) {
    int i = blockIdx.x * blockDim.x + threadIdx.x;
    if (i < NC_ * 256) {
        float s = G1[i] * rsqrtf(V1[i] + EPSBN);
        g_sc1[i] = s; g_sh1[i] = Bb1[i] - M1[i] * s;
    } else if (i < NC_ * 256 + NC_ * 128) {
        int j = i - NC_ * 256;
        float s = G2[j] * rsqrtf(V2[j] + EPSBN);
        g_sc2[j] = s; g_sh2[j] = Bb2[j] - M2[j] * s;
    }
}

// ---------------- weight-row table (for wsplit2) -----------------------------------------
__global__ void k_tables() {
    int i = blockIdx.x * blockDim.x + threadIdx.x;
    if (i < 4 * 2304) {
        int par = i / 2304, q = i - par * 2304;
        int a = par >> 1, pb = par & 1;
        int nh = a ? 3 : 2, nw = pb ? 3 : 2;
        int Kp = nh * nw * 256;
        if (q < Kp) {
            int th = q / (nw * 256);
            int r = q - th * (nw * 256);
            int tw = r / 256, ci = r & 255;
            int kh = 2 * th + (a ? 0 : 1);
            int kw = 2 * tw + (pb ? 0 : 1);
            g_wrow2[par * 2304 + q] = (kh * 5 + kw) * 256 + ci;
        }
    }
}

// ---------------- embedding bias precompute ----------------------------------------------
// TB[c][tap][co] = sum_e emb[c][e] * K1[c][tap][256+e][co]
__global__ void k_bias1(const float* __restrict__ emb, const float* __restrict__ K1) {
    int co = threadIdx.x;
    int tap = blockIdx.x, c = blockIdx.y;
    const float* kp = K1 + ((size_t)(c * 25 + tap) * 306 + 256) * 256 + co;
    const float* ep = emb + c * EMB_;
    float s = 0.f;
#pragma unroll 10
    for (int e = 0; e < EMB_; e++) s += ep[e] * kp[(size_t)e * 256];
    g_tb1[(c * 25 + tap) * 256 + co] = s;
}
// PB[c][pos][co] = sum over valid taps of TB
__global__ void k_bias2() {
    int co = threadIdx.x;
    int pos = blockIdx.x, c = blockIdx.y;
    int h = pos / 7, w = pos - h * 7;
    int khl = (2 - h) > 0 ? (2 - h) : 0, khh = (8 - h) < 4 ? (8 - h) : 4;
    int kwl = (2 - w) > 0 ? (2 - w) : 0, kwh = (8 - w) < 4 ? (8 - w) : 4;
    float s = 0.f;
    for (int kh = khl; kh <= khh; kh++)
        for (int kw = kwl; kw <= kwh; kw++)
            s += g_tb1[(c * 25 + kh * 5 + kw) * 256 + co];
    g_pb1[(c * 49 + pos) * 256 + co] = s;
}

// ---------------- weight transpose + hi/lo split -----------------------------------------
// K1 feature part only: k = tap*256+ci (ci<256) -> W1 [c][co][6400]
__global__ void k_wsplit1(const float* __restrict__ K1) {
    __shared__ float s[64][33];
    int cot = blockIdx.x, kt = blockIdx.y, c = blockIdx.z;
    int tid = threadIdx.x;
#pragma unroll
    for (int l = 0; l < 8; l++) {
        int idx = tid + l * 256;
        int kk = idx >> 5, coI = idx & 31;
        int k = kt * 64 + kk;
        int tap = k >> 8, ci = k & 255;
        s[kk][coI] = K1[((size_t)(c * 25 + tap) * 306 + ci) * 256 + cot * 32 + coI];
    }
    __syncthreads();
#pragma unroll
    for (int l = 0; l < 8; l++) {
        int idx = tid + l * 256;
        int co2 = idx >> 6, k2 = idx & 63;
        float v = s[k2][co2];
        __nv_bfloat16 hi = __float2bfloat16(v);
        __nv_bfloat16 lo = __float2bfloat16(v - __bfloat162float(hi));
        size_t o = ((size_t)(c * 256 + cot * 32 + co2)) * 6400 + kt * 64 + k2;
        g_W1h[o] = hi; g_W1l[o] = lo;
    }
}

__global__ void k_wsplit2(const float* __restrict__ K2) {
    __shared__ float s[64][33];
    int par = blockIdx.x >> 2, cot = blockIdx.x & 3;
    int kt = blockIdx.y, c = blockIdx.z;
    int Kp = (2 + (par >> 1)) * (2 + (par & 1)) * 256;
    int tid = threadIdx.x;
#pragma unroll
    for (int l = 0; l < 8; l++) {
        int idx = tid + l * 256;
        int kk = idx >> 5, coI = idx & 31;
        int k = kt * 64 + kk;
        float v = 0.f;
        if (k < Kp) {
            int row = g_wrow2[par * 2304 + k];
            v = K2[((size_t)c * 6400 + row) * 128 + cot * 32 + coI];
        }
        s[kk][coI] = v;
    }
    __syncthreads();
#pragma unroll
    for (int l = 0; l < 8; l++) {
        int idx = tid + l * 256;
        int co2 = idx >> 6, k2 = idx & 63;
        float v = s[k2][co2];
        __nv_bfloat16 hi = __float2bfloat16(v);
        __nv_bfloat16 lo = __float2bfloat16(v - __bfloat162float(hi));
        size_t o = ((size_t)((c * 4 + par) * 128 + cot * 32 + co2)) * 2304 + kt * 64 + k2;
        g_W2h[o] = hi; g_W2l[o] = lo;
    }
}

// ---------------- dense GEMM + bn + lrelu -> x0 hi/lo bf16 (256 chan) --------------------
__global__ __launch_bounds__(256) void k_dense(const float* __restrict__ Wd) {
    __shared__ float As[2][TK][TM + 4];
    __shared__ float Bs[2][TK][TN];
    int tid = threadIdx.x, tx = tid & 15, ty = tid >> 4;
    int row0 = blockIdx.y * TM;
    int col0 = blockIdx.x * TN;
    int ar = tid >> 2, ak = (tid & 3) * 4;
    int bkk = tid >> 4, bn = (tid & 15) * 4;
    const float* arow = g_xin + (size_t)(row0 + ar) * KIN_PAD;

    u64 acc[4][2];
#pragma unroll
    for (int i = 0; i < 4; i++) { acc[i][0] = 0ull; acc[i][1] = 0ull; }

    const int nT = KIN_PAD / TK;
    float a_reg[4]; float4 b_reg;
    {
#pragma unroll
        for (int i = 0; i < 4; i++) a_reg[i] = arow[ak + i];
        int k = bkk;
        b_reg = (k < KIN) ? *(const float4*)(Wd + (size_t)k * DENSE_N + col0 + bn)
                          : make_float4(0.f, 0.f, 0.f, 0.f);
    }
    int buf = 0;
    for (int t = 0; t < nT; t++) {
#pragma unroll
        for (int i = 0; i < 4; i++) As[buf][ak + i][ar] = a_reg[i];
        *(float4*)&Bs[buf][bkk][bn] = b_reg;
        __syncthreads();
        if (t + 1 < nT) {
            int k0 = (t + 1) * TK;
#pragma unroll
            for (int i = 0; i < 4; i++) a_reg[i] = arow[k0 + ak + i];
            int k = k0 + bkk;
            b_reg = (k < KIN) ? *(const float4*)(Wd + (size_t)k * DENSE_N + col0 + bn)
                              : make_float4(0.f, 0.f, 0.f, 0.f);
        }
#pragma unroll
        for (int kk = 0; kk < TK; kk++) {
            float4 av = *(const float4*)&As[buf][kk][ty * 4];
            u64 b0 = *(const u64*)&Bs[buf][kk][tx * 4];
            u64 b1 = *(const u64*)&Bs[buf][kk][tx * 4 + 2];
            float aa[4] = {av.x, av.y, av.z, av.w};
#pragma unroll
            for (int i = 0; i < 4; i++) {
                u64 ad = pk2(aa[i], aa[i]);
                acc[i][0] = ffma2(ad, b0, acc[i][0]);
                acc[i][1] = ffma2(ad, b1, acc[i][1]);
            }
        }
        __syncthreads();
        buf ^= 1;
    }
#pragma unroll
    for (int i = 0; i < 4; i++) {
        int b = row0 + ty * 4 + i;
        float y4[4];
        upk2(acc[i][0], y4[0], y4[1]);
        upk2(acc[i][1], y4[2], y4[3]);
        int jc0 = col0 + tx * 4;
#pragma unroll
        for (int j = 0; j < 4; j++) {
            int jc = jc0 + j;
            float y = y4[j] * g_scale1[jc] + g_shift1[jc];
            y4[j] = (y >= 0.f) ? y : ALPHA * y;
        }
        int h = jc0 / 1792;
        int w = (jc0 >> 8) % 7;
        int ch = jc0 & 255;
        size_t xb = ((size_t)(b * 11 + h + 2) * 11 + (w + 2)) * 256 + ch;
        float hi0 = __bfloat162float(__float2bfloat16(y4[0]));
        float hi1 = __bfloat162float(__float2bfloat16(y4[1]));
        float hi2 = __bfloat162float(__float2bfloat16(y4[2]));
        float hi3 = __bfloat162float(__float2bfloat16(y4[3]));
        *(u32*)&g_x0h[xb]     = packbf(y4[0], y4[1]);
        *(u32*)&g_x0h[xb + 2] = packbf(y4[2], y4[3]);
        *(u32*)&g_x0l[xb]     = packbf(y4[0] - hi0, y4[1] - hi1);
        *(u32*)&g_x0l[xb + 2] = packbf(y4[2] - hi2, y4[3] - hi3);
    }
}

// ---------------- fused 3-combo bf16 mma gather-GEMM with tap skipping -------------------
// Rows ordered position-major within each class so a 64-row tile spans few raster
// positions; per-tile the union of valid (non-padding) taps is computed and K is
// iterated as (tap, 8 x 32-slab) over that list only. Invalid taps for some rows in
// the tile read zero padding (+0.0f -> exact); wholly-invalid taps are skipped.
__global__ __launch_bounds__(256, 3) void k_mma(int mode) {
    __shared__ __nv_bfloat16 P[2 * PLANE_A + 2 * PLANE_BN];   // Ah,Al(64r) Bh,Bl(128r)
    __shared__ int sAidx[64];
    __shared__ int sTapA[25], sTapB[25];
    __shared__ int sNtap;

    int c = blockIdx.z;
    int s0 = g_cstart[c];
    int cnt = g_cstart[c + 1] - s0;
    int rows = cnt * 49;
    int row0 = blockIdx.y * 64;
    if (row0 >= rows) return;

    const __nv_bfloat16 *Ahp, *Alp, *Bhp, *Blp;
    int N, Wstride, col0;
    int a_bs, a_pw;
    int ntapFull, nw_;
    const float *sc, *sh;
    const float* pbp = 0;
    int o_bs, o_rs, o_h0, o_hs, o_w0, o_ws;
    if (mode == 0) {
        Ahp = g_x0h; Alp = g_x0l;
        col0 = blockIdx.x * 128;
        Bhp = g_W1h + (size_t)(c * 256 + col0) * 6400;
        Blp = g_W1l + (size_t)(c * 256 + col0) * 6400;
        Wstride = 6400; N = 256;
        a_bs = 121 * 256; a_pw = 11;
        ntapFull = 25; nw_ = 5;
        sc = g_sc1 + c * 256; sh = g_sh1 + c * 256;
        pbp = g_pb1 + (size_t)c * 49 * 256;
        o_bs = 81 * 256; o_rs = 9 * 256; o_h0 = 1; o_hs = 1; o_w0 = 1; o_ws = 1;
    } else {
        int par = blockIdx.x;
        Ahp = g_h1h; Alp = g_h1l;
        col0 = 0;
        Bhp = g_W2h + (size_t)((c * 4 + par) * 128) * 2304;
        Blp = g_W2l + (size_t)((c * 4 + par) * 128) * 2304;
        Wstride = 2304; N = 128;
        a_bs = 81 * 256; a_pw = 9;
        int nh = 2 + (par >> 1);
        nw_ = 2 + (par & 1);
        ntapFull = nh * nw_;
        sc = g_sc2 + c * 128; sh = g_sh2 + c * 128;
        o_bs = 256 * 128; o_rs = 16 * 128;
        o_h0 = (par >> 1) + 1; o_hs = 2; o_w0 = (par & 1) + 1; o_ws = 2;
    }

    __nv_bfloat16* Ahs = P;
    __nv_bfloat16* Als = P + PLANE_A;
    __nv_bfloat16* Bhs = P + 2 * PLANE_A;
    __nv_bfloat16* Bls = P + 2 * PLANE_A + PLANE_BN;

    int tid = threadIdx.x;
    // per-row gather base (position-major: r = pos*cnt + sl)
    if (tid < 64) {
        int r = row0 + tid;
        int ai = -1;
        if (r < rows) {
            int pos = r / cnt, sl = r - pos * cnt;
            int b = g_order[s0 + sl];
            int h = pos / 7, w = pos - h * 7;
            ai = b * a_bs + (h * a_pw + w) * 256;
        }
        sAidx[tid] = ai;
    }
    // tap union for this tile (warp 1: lanes 0..24 = taps)
    if (tid >= 32 && tid < 64) {
        int lane = tid - 32;
        int rLast = row0 + 63;
        if (rLast > rows - 1) rLast = rows - 1;
        int p0 = row0 / cnt;
        int p1 = rLast / cnt;
        bool val = false;
        if (lane < ntapFull) {
            for (int p = p0; p <= p1; p++) {
                int h = p / 7, w = p - (p / 7) * 7;
                bool ok;
                if (mode == 0) {
                    int kh = lane / 5, kw = lane - (lane / 5) * 5;
                    ok = (kh >= 2 - h) && (kh <= 8 - h) && (kw >= 2 - w) && (kw <= 8 - w);
                } else {
                    int th = lane / nw_, tw = lane - (lane / nw_) * nw_;
                    ok = (th >= 1 - h) && (th <= 7 - h) && (tw >= 1 - w) && (tw <= 7 - w);
                }
                val = val || ok;
            }
        }
        unsigned msk = __ballot_sync(0xFFFFFFFFu, val);
        if (lane == 0) {
            int n = 0;
            while (msk) {
                int tap = __ffs(msk) - 1;
                msk &= msk - 1;
                int aB;
                if (mode == 0) aB = ((tap / 5) * 11 + (tap - (tap / 5) * 5)) * 256;
                else           aB = ((tap / nw_) * 9 + (tap - (tap / nw_) * nw_)) * 256;
                sTapA[n] = aB;
                sTapB[n] = tap * 256;
                n++;
            }
            sNtap = n;
        }
    }
    __syncthreads();
    int nS = sNtap * 8;

    // fill assignments (lanes sweep k within a row)
    int kq = (tid & 15) * 2;        // A: k pair within 32-slab
    int rA = tid >> 4;              // A: rows rA + j*16, j<4
    int bq = (tid & 3) * 8;         // B: 8-elem (16B) quarter of 32-slab
    int rB = tid >> 2;              // B: rows rB + j*64, j<2
    int aidxA[4];
#pragma unroll
    for (int j = 0; j < 4; j++) aidxA[j] = sAidx[rA + j * 16];

    // warp / fragment ids: 8 warps as 2(m) x 4(n)
    int wid = tid >> 5, lane = tid & 31;
    int g = lane >> 2, tg = lane & 3;
    int wm = (wid >> 2) * 32, wn = (wid & 3) * 32;

    float acc[2][4][4];
#pragma unroll
    for (int mi = 0; mi < 2; mi++)
#pragma unroll
        for (int ni = 0; ni < 4; ni++)
#pragma unroll
            for (int q = 0; q < 4; q++) acc[mi][ni][q] = 0.f;

    u32 pah[4], pal[4];

    // prefetch slab 0
    {
        int ao = sTapA[0] + kq;
#pragma unroll
        for (int j = 0; j < 4; j++) {
            pah[j] = (aidxA[j] >= 0) ? *(const u32*)(Ahp + aidxA[j] + ao) : 0u;
            pal[j] = (aidxA[j] >= 0) ? *(const u32*)(Alp + aidxA[j] + ao) : 0u;
        }
    }

    for (int q = 0; q < nS; q++) {
        int bB = sTapB[q >> 3] + (q & 7) * 32;
        // store A (from prefetch regs)
#pragma unroll
        for (int j = 0; j < 4; j++) {
            int off = (rA + j * 16) * PIT + kq;
            *(u32*)&Ahs[off] = pah[j];
            *(u32*)&Als[off] = pal[j];
        }
        // load + store B (short-lived regs)
#pragma unroll
        for (int j = 0; j < 2; j++) {
            int row = rB + j * 64;
            size_t se = (size_t)row * Wstride + bB + bq;
            uint4 vh = *(const uint4*)(Bhp + se);
            uint4 vl = *(const uint4*)(Blp + se);
            *(uint4*)&Bhs[row * PIT + bq] = vh;
            *(uint4*)&Bls[row * PIT + bq] = vl;
        }
        __syncthreads();
        // prefetch A for next slab (overlaps compute)
        if (q + 1 < nS) {
            int ao = sTapA[(q + 1) >> 3] + ((q + 1) & 7) * 32 + kq;
#pragma unroll
            for (int j = 0; j < 4; j++) {
                pah[j] = (aidxA[j] >= 0) ? *(const u32*)(Ahp + aidxA[j] + ao) : 0u;
                pal[j] = (aidxA[j] >= 0) ? *(const u32*)(Alp + aidxA[j] + ao) : 0u;
            }
        }
#pragma unroll
        for (int ks = 0; ks < 2; ks++) {
            int kb16 = ks * 16;
            u32 bf[4][2];
            // phase 1: Bh combos (Ah*Bh, Al*Bh)
#pragma unroll
            for (int ni = 0; ni < 4; ni++) {
                const __nv_bfloat16* bp = &Bhs[(wn + ni * 8 + g) * PIT + kb16 + tg * 2];
                bf[ni][0] = *(const u32*)bp;
                bf[ni][1] = *(const u32*)(bp + 8);
            }
#pragma unroll
            for (int mi = 0; mi < 2; mi++) {
                const __nv_bfloat16* ap = &Ahs[(wm + mi * 16 + g) * PIT + kb16 + tg * 2];
                u32 a0 = *(const u32*)ap;
                u32 a1 = *(const u32*)(ap + 8 * PIT);
                u32 a2 = *(const u32*)(ap + 8);
                u32 a3 = *(const u32*)(ap + 8 * PIT + 8);
                const __nv_bfloat16* lp = &Als[(wm + mi * 16 + g) * PIT + kb16 + tg * 2];
                u32 l0 = *(const u32*)lp;
                u32 l1 = *(const u32*)(lp + 8 * PIT);
                u32 l2 = *(const u32*)(lp + 8);
                u32 l3 = *(const u32*)(lp + 8 * PIT + 8);
#pragma unroll
                for (int ni = 0; ni < 4; ni++) {
                    mma16816(acc[mi][ni], a0, a1, a2, a3, bf[ni][0], bf[ni][1]);
                    mma16816(acc[mi][ni], l0, l1, l2, l3, bf[ni][0], bf[ni][1]);
                }
            }
            // phase 2: Bl combo (Ah*Bl)
#pragma unroll
            for (int ni = 0; ni < 4; ni++) {
                const __nv_bfloat16* bp = &Bls[(wn + ni * 8 + g) * PIT + kb16 + tg * 2];
                bf[ni][0] = *(const u32*)bp;
                bf[ni][1] = *(const u32*)(bp + 8);
            }
#pragma unroll
            for (int mi = 0; mi < 2; mi++) {
                const __nv_bfloat16* ap = &Ahs[(wm + mi * 16 + g) * PIT + kb16 + tg * 2];
                u32 a0 = *(const u32*)ap;
                u32 a1 = *(const u32*)(ap + 8 * PIT);
                u32 a2 = *(const u32*)(ap + 8);
                u32 a3 = *(const u32*)(ap + 8 * PIT + 8);
#pragma unroll
                for (int ni = 0; ni < 4; ni++)
                    mma16816(acc[mi][ni], a0, a1, a2, a3, bf[ni][0], bf[ni][1]);
            }
        }
        __syncthreads();
    }

    // epilogue: (+PB for mode0) bn + lrelu; mode0 -> h1 hi/lo bf16, mode1 -> h2 fp32
#pragma unroll
    for (int mi = 0; mi < 2; mi++) {
#pragma unroll
        for (int hh = 0; hh < 2; hh++) {
            int lr = wm + mi * 16 + g + hh * 8;
            int r = row0 + lr;
            if (r >= rows) continue;
            int pos = r / cnt, sl = r - pos * cnt;
            int b = g_order[s0 + sl];
            int h = pos / 7, w = pos - h * 7;
            size_t ob = (size_t)b * o_bs + (size_t)(o_h0 + h * o_hs) * o_rs
                      + (size_t)(o_w0 + w * o_ws) * (size_t)N;
            const float* pbrow = pbp ? (pbp + pos * 256) : 0;
#pragma unroll
            for (int ni = 0; ni < 4; ni++) {
                int co = wn + ni * 8 + tg * 2;
                int gco = col0 + co;
                float v0 = acc[mi][ni][hh * 2 + 0];
                float v1 = acc[mi][ni][hh * 2 + 1];
                if (pbrow) { v0 += pbrow[gco]; v1 += pbrow[gco + 1]; }
                v0 = v0 * sc[gco] + sh[gco];
                v1 = v1 * sc[gco + 1] + sh[gco + 1];
                v0 = (v0 >= 0.f) ? v0 : ALPHA * v0;
                v1 = (v1 >= 0.f) ? v1 : ALPHA * v1;
                if (mode == 0) {
                    float h0 = __bfloat162float(__float2bfloat16(v0));
                    float h1 = __bfloat162float(__float2bfloat16(v1));
                    *(u32*)&g_h1h[ob + gco] = packbf(v0, v1);
                    *(u32*)&g_h1l[ob + gco] = packbf(v0 - h0, v1 - h1);
                } else {
                    *(float2*)&g_h2[ob + gco] = make_float2(v0, v1);
                }
            }
        }
    }
}

// ---------------- ConvT3 (N=1) + tanh ----------------------------------------------------
__global__ __launch_bounds__(256) void k_convt3(const float* __restrict__ K3,
                                                const int* __restrict__ labels,
                                                float* __restrict__ out) {
    int b = blockIdx.x;
    int c = labels[b];
    __shared__ float Ks[5 * 5 * 128];
    for (int i = threadIdx.x; i < 5 * 5 * 128; i += blockDim.x)
        Ks[i] = K3[c * (5 * 5 * 128) + i];
    __syncthreads();
    const float* hb = g_h2 + (size_t)b * 16 * 16 * 128;
    for (int p = threadIdx.x; p < 784; p += blockDim.x) {
        int oh = p / 28, ow = p - oh * 28;
        int i = oh >> 1, a = oh & 1, j = ow >> 1, pb = ow & 1;
        int nh = a ? 3 : 2, nw = pb ? 3 : 2;
        float acc = 0.f;
        for (int th = 0; th < nh; th++) {
            int kh = 2 * th + (a ? 0 : 1);
            int ph = i + th;
            for (int tw = 0; tw < nw; tw++) {
                int kw = 2 * tw + (pb ? 0 : 1);
                int pw = j + tw;
                const float* xp = hb + (size_t)(ph * 16 + pw) * 128;
                const float* wp = Ks + (kh * 5 + kw) * 128;
#pragma unroll
                for (int ci = 0; ci < 128; ci += 4) {
                    float4 xv = *(const float4*)(xp + ci);
                    float4 wv = *(const float4*)(wp + ci);
                    acc += xv.x * wv.x + xv.y * wv.y + xv.z * wv.z + xv.w * wv.w;
                }
            }
        }
        out[(size_t)b * 784 + p] = tanhf(acc);
    }
}

// ---------------- launch ----------------------------------------------------------------
extern "C" void kernel_launch(void* const* d_in, const int* in_sizes, int n_in,
                              void* d_out, int out_size) {
    const float* noise = (const float*)d_in[0];
    const int*   labels = (const int*)d_in[1];
    const float* emb  = (const float*)d_in[2];
    const float* Wd   = (const float*)d_in[3];
    const float* bn1_g = (const float*)d_in[4];
    const float* bn1_b = (const float*)d_in[5];
    const float* bn1_m = (const float*)d_in[6];
    const float* bn1_v = (const float*)d_in[7];
    const float* K1 = (const float*)d_in[8];
    const float* G1 = (const float*)d_in[9];
    const float* B1 = (const float*)d_in[10];
    const float* M1 = (const float*)d_in[11];
    const float* V1 = (const float*)d_in[12];
    const float* K2 = (const float*)d_in[13];
    const float* G2 = (const float*)d_in[14];
    const float* B2 = (const float*)d_in[15];
    const float* M2 = (const float*)d_in[16];
    const float* V2 = (const float*)d_in[17];
    const float* K3 = (const float*)d_in[18];
    float* out = (float*)d_out;

    k_classify<<<1, B_>>>(labels);
    k_xin<<<(B_ * KIN + 255) / 256, 256>>>(noise, emb, labels);
    k_bnscale1<<<(DENSE_N + 255) / 256, 256>>>(bn1_g, bn1_b, bn1_m, bn1_v);
    k_bnbranch<<<(NC_ * 256 + NC_ * 128 + 255) / 256, 256>>>(G1, B1, M1, V1, G2, B2, M2, V2);
    k_tables<<<(4 * 2304 + 255) / 256, 256>>>();

    k_wsplit1<<<dim3(8, 100, NC_), 256>>>(K1);
    k_wsplit2<<<dim3(16, 36, NC_), 256>>>(K2);
    k_bias1<<<dim3(25, NC_), 256>>>(emb, K1);
    k_bias2<<<dim3(49, NC_), 256>>>();

    k_dense<<<dim3(DENSE_N / TN, B_ / TM), 256>>>(Wd);

    // ConvT1: 2 col tiles x 64-row tiles x classes (empty tiles exit)
    k_mma<<<dim3(2, (B_ * 49 + 63) / 64, NC_), 256>>>(0);
    // ConvT2: 4 parities x 64-row tiles x classes
    k_mma<<<dim3(4, (B_ * 49 + 63) / 64, NC_), 256>>>(1);

    k_convt3<<<B_, 256>>>(K3, labels, out);
    (void)in_sizes; (void)n_in; (void)out_size;
}